// round 10
// baseline (speedup 1.0000x reference)
#include <cuda_runtime.h>
#include <cstdint>

#define BB 64
#define TT 512
#define EE 256
#define H4 1024
#define KK 9

typedef unsigned long long ull;

// ---------------- device scratch (static) ----------------
// ih weights (idx 0,1): paired layout  float[((k>>1)*H4 + j)*2 + (k&1)]  == ull[k2*H4 + j]
// hh weights (idx 2,3): plain          float[k*H4 + j]
__device__ float g_wt[4][EE * H4];
__device__ float g_xp[2 * TT * BB * H4];       // [dir][step][b][j]
__device__ float g_seq[(size_t)BB * TT * 512]; // [b][t][2H]
__device__ float g_logits[BB * TT * KK];
__device__ float g_llh[BB];

__device__ __forceinline__ float fsig(float x) {
    return __fdividef(1.0f, 1.0f + __expf(-x));
}
__device__ __forceinline__ float ftanh(float x) {
    return __fdividef(2.0f, 1.0f + __expf(-2.0f * x)) - 1.0f;
}

__device__ __forceinline__ void fma2(ull& d, ull a, ull b) {
    asm("fma.rn.f32x2 %0, %1, %2, %0;" : "+l"(d) : "l"(a), "l"(b));
}
__device__ __forceinline__ float hsum2(ull v) {
    float lo, hi;
    asm("mov.b64 {%0,%1}, %2;" : "=f"(lo), "=f"(hi) : "l"(v));
    return lo + hi;
}

__device__ __forceinline__ uint32_t smem_u32(const void* p) {
    uint32_t a;
    asm("{ .reg .u64 t; cvta.to.shared.u64 t, %1; cvt.u32.u64 %0, t; }" : "=r"(a) : "l"(p));
    return a;
}
// store one float into the same smem offset of cluster CTA `rank`
__device__ __forceinline__ void dsmem_st(uint32_t local_addr, int rank, float v) {
    asm volatile(
        "{ .reg .u32 r%=; mapa.shared::cluster.u32 r%=, %0, %1; st.shared::cluster.f32 [r%=], %2; }"
        :: "r"(local_addr), "r"(rank), "f"(v) : "memory");
}
__device__ __forceinline__ void mbar_init(uint32_t a, uint32_t cnt) {
    asm volatile("mbarrier.init.shared.b64 [%0], %1;" :: "r"(a), "r"(cnt) : "memory");
}
// release-arrive on the mbarrier at the same smem offset in cluster CTA `rank`
__device__ __forceinline__ void mbar_arrive_cluster(uint32_t local_bar, int rank) {
    asm volatile(
        "{ .reg .u32 r%=; mapa.shared::cluster.u32 r%=, %0, %1; "
        "mbarrier.arrive.release.cluster.shared::cluster.b64 _, [r%=]; }"
        :: "r"(local_bar), "r"(rank) : "memory");
}
__device__ __forceinline__ void mbar_wait(uint32_t a, uint32_t parity) {
    asm volatile(
        "{ .reg .pred p%=;\n"
        "LW%=: mbarrier.try_wait.parity.acquire.cluster.shared::cta.b64 p%=, [%0], %1, 0x989680;\n"
        "@p%= bra LD%=;\n"
        "bra LW%=;\n"
        "LD%=: }"
        :: "r"(a), "r"(parity) : "memory");
}

// ---------------- kernel 1: weight transpose/pack ----------------
__global__ void transpose_w_kernel(const float* __restrict__ wf, const float* __restrict__ wb,
                                   const float* __restrict__ whf, const float* __restrict__ whb) {
    int idx = blockIdx.x * 256 + threadIdx.x;      // 4 * 262144 total
    int srcid = idx >> 18;
    int m = idx & 262143;
    int k = m >> 10;
    int j = m & 1023;
    const float* src = (srcid == 0) ? wf : (srcid == 1) ? wb : (srcid == 2) ? whf : whb;
    float v = src[j * EE + k];
    if (srcid < 2) g_wt[srcid][((k >> 1) * H4 + j) * 2 + (k & 1)] = v;   // paired over k
    else           g_wt[srcid][k * H4 + j] = v;                          // plain
}

// ---------------- kernel 2: embedding gather + input projections (f32x2) ----------------
__global__ void __launch_bounds__(256, 1) proj_kernel(const int* __restrict__ word_ids,
                                                      const float* __restrict__ embed,
                                                      const float* __restrict__ b_f,
                                                      const float* __restrict__ b_b) {
    extern __shared__ float psm[];
    float* esf = psm;                 // [32][256]   = 8192 floats
    ull*   wsm = (ull*)(psm + 8192);  // [64 k2][256 j] ull = 32768 floats
    __shared__ int wids[32];

    int dir = blockIdx.z;
    int jt  = blockIdx.y;             // j base jt*256
    int tile = blockIdx.x;
    int s  = tile >> 1;
    int b0 = (tile & 1) * 32;
    int t_src = dir ? (TT - 1 - s) : s;
    int tid = threadIdx.x;
    int jb = jt * 256;

    if (tid < 32) wids[tid] = word_ids[(b0 + tid) * TT + t_src];
    __syncthreads();
    for (int i = tid; i < 2048; i += 256) {
        int r = i >> 6, c = i & 63;
        ((float4*)&esf[r * 256])[c] = ((const float4*)(embed + (size_t)wids[r] * EE))[c];
    }

    int tg = tid >> 6;                // 0..3 -> tokens tg*8..tg*8+7
    int jq = tid & 63;                // -> j cols jb + jq*4 .. +3

    ull acc[8][4];
#pragma unroll
    for (int r = 0; r < 8; r++)
#pragma unroll
        for (int c = 0; c < 4; c++) acc[r][c] = 0ull;

    const float4* __restrict__ gw4 = (const float4*)g_wt[dir];

    for (int kc = 0; kc < 2; kc++) {
        __syncthreads();
        for (int i = tid; i < 8192; i += 256) {
            int k2l = i >> 7;
            int jj4 = i & 127;
            ((float4*)wsm)[i] = gw4[((size_t)((kc * 64 + k2l) * H4 + jb) >> 1) + jj4];
        }
        __syncthreads();

#pragma unroll 4
        for (int k2l = 0; k2l < 64; k2l += 2) {
            int kabs4 = kc * 128 + 2 * k2l;
            ulonglong2 a[8];
#pragma unroll
            for (int r = 0; r < 8; r++)
                a[r] = *(const ulonglong2*)&esf[(tg * 8 + r) * 256 + kabs4];
            const ull* wpA = &wsm[k2l * 256 + jq * 4];
            const ull* wpB = &wsm[(k2l + 1) * 256 + jq * 4];
            ulonglong2 wA01 = *(const ulonglong2*)wpA;
            ulonglong2 wA23 = *(const ulonglong2*)(wpA + 2);
            ulonglong2 wB01 = *(const ulonglong2*)wpB;
            ulonglong2 wB23 = *(const ulonglong2*)(wpB + 2);
#pragma unroll
            for (int r = 0; r < 8; r++) {
                fma2(acc[r][0], a[r].x, wA01.x);
                fma2(acc[r][1], a[r].x, wA01.y);
                fma2(acc[r][2], a[r].x, wA23.x);
                fma2(acc[r][3], a[r].x, wA23.y);
                fma2(acc[r][0], a[r].y, wB01.x);
                fma2(acc[r][1], a[r].y, wB01.y);
                fma2(acc[r][2], a[r].y, wB23.x);
                fma2(acc[r][3], a[r].y, wB23.y);
            }
        }
    }

    const float* bias_p = dir ? b_b : b_f;
    int j0 = jb + jq * 4;
    float4 bias = *(const float4*)&bias_p[j0];
    size_t base = ((size_t)dir * TT + s) * (BB * H4);
#pragma unroll
    for (int r = 0; r < 8; r++) {
        int b = b0 + tg * 8 + r;
        float4 v;
        v.x = hsum2(acc[r][0]) + bias.x;
        v.y = hsum2(acc[r][1]) + bias.y;
        v.z = hsum2(acc[r][2]) + bias.z;
        v.w = hsum2(acc[r][3]) + bias.w;
        *(float4*)&g_xp[base + (size_t)b * H4 + j0] = v;
    }
}

// ---------------- kernel 3: persistent BiLSTM, DSMEM h-exchange, f32x2 ----------------
// grid (64, 2), cluster (8,1,1): cluster = the 8 CTAs of one (dir, batch-tile) group.
// CTA (bt, et): 8 batch rows x 32 e-cols (all 4 gates local).
// h exchange: each CTA pushes its 8x32 h tile into all 8 cluster peers' hs buffer
// via st.shared::cluster, then release-arrives on each peer's mbarrier (count=8).
// No barrier.cluster in the loop -> no per-step L1D flush.
__global__ void __launch_bounds__(256, 1) __cluster_dims__(8, 1, 1) lstm_kernel() {
    extern __shared__ float sm[];
    ull*   ws2 = (ull*)sm;            // [128 k2][128 col] ull  (131072 B)
    float* hsb[2];
    hsb[0] = sm + 32768;              // [8][256]  (8192 B)
    hsb[1] = sm + 32768 + 2048;       // [8][256]  (8192 B)
    float* gxp = sm + 32768 + 4096;   // [4 kh][8 row][128 col] (16384 B)
    ull*   mbar = (ull*)(sm + 32768 + 4096 + 4096);   // 2 mbarriers

    int dir = blockIdx.y;
    int cta = blockIdx.x;
    int bt = cta >> 3;
    int et = cta & 7;
    int b_base = bt * 8;
    int tid = threadIdx.x;

    // GEMM thread mapping
    int jp = tid & 63;                // cols 2jp, 2jp+1  (col = g*32+el)
    int kh = tid >> 6;                // k2 in [kh*32, kh*32+32)

    // elementwise mapping
    int bl = tid >> 5;                // 0..7
    int el2 = tid & 31;
    int b_e = b_base + bl;
    int e = et * 32 + el2;

    uint32_t mbar_a = smem_u32(mbar);
    if (tid == 0) {
        mbar_init(mbar_a, 8);
        mbar_init(mbar_a + 8, 8);
    }

    // stage W_hh^T slice as k-pairs: ws2[k2*128 + col] = {w[2k2][C], w[2k2+1][C]}
    const float* __restrict__ whh_t = g_wt[2 + dir];
    float* wsf = sm;
    for (int i = tid; i < 32768; i += 256) {
        int k = i >> 7, col = i & 127;
        float v = whh_t[k * H4 + (col >> 5) * 256 + et * 32 + (col & 31)];
        wsf[((k >> 1) * 128 + col) * 2 + (k & 1)] = v;
    }
    // zero h buffer 0
    for (int i = tid; i < 2048; i += 256) hsb[0][i] = 0.0f;
    __syncthreads();

    // cluster sync once: mbarriers visible before any remote arrive
    asm volatile("barrier.cluster.arrive.aligned;" ::: "memory");
    asm volatile("barrier.cluster.wait.aligned;" ::: "memory");

    // dsmem slot for my h value in buffer 0/1 (same offset in every peer's smem)
    uint32_t slot[2];
    slot[0] = smem_u32(&hsb[0][bl * 256 + e]);
    slot[1] = smem_u32(&hsb[1][bl * 256 + e]);

    float c_reg = 0.0f;

    for (int s = 0; s < TT; s++) {
        int buf = s & 1;
        const float* hs = hsb[buf];

        // prefetch xp (independent of h; overlaps the wait + GEMM)
        const float* __restrict__ xpp = g_xp + ((size_t)dir * TT + s) * (BB * H4);
        float xq0 = xpp[(size_t)b_e * H4 + 0 * 256 + e];
        float xq1 = xpp[(size_t)b_e * H4 + 1 * 256 + e];
        float xq2 = xpp[(size_t)b_e * H4 + 2 * 256 + e];
        float xq3 = xpp[(size_t)b_e * H4 + 3 * 256 + e];

        if (s > 0) {
            uint32_t ph = ((s - 1) >> 1) & 1;   // completion parity of mbar[buf]
            mbar_wait(mbar_a + 8u * buf, ph);
        }

        // GEMM: this thread's k-slice, 2 cols, all 8 rows; 2 k2 per iter
        ull acc[8][2];
#pragma unroll
        for (int r = 0; r < 8; r++) { acc[r][0] = 0ull; acc[r][1] = 0ull; }

        int k2b = kh * 32;
#pragma unroll 4
        for (int k2i = 0; k2i < 32; k2i += 2) {
            int k2 = k2b + k2i;
            ulonglong2 wA = *(const ulonglong2*)&ws2[k2 * 128 + 2 * jp];
            ulonglong2 wB = *(const ulonglong2*)&ws2[(k2 + 1) * 128 + 2 * jp];
#pragma unroll
            for (int r = 0; r < 8; r++) {
                ulonglong2 a = *(const ulonglong2*)&hs[r * 256 + 2 * k2];
                fma2(acc[r][0], a.x, wA.x);
                fma2(acc[r][1], a.x, wA.y);
                fma2(acc[r][0], a.y, wB.x);
                fma2(acc[r][1], a.y, wB.y);
            }
        }
        // write k-partials to exchange smem
#pragma unroll
        for (int r = 0; r < 8; r++) {
            float2 pv;
            pv.x = hsum2(acc[r][0]);
            pv.y = hsum2(acc[r][1]);
            *(float2*)&gxp[kh * 1024 + r * 128 + 2 * jp] = pv;
        }
        __syncthreads();

        // elementwise update (c in register), reduce 4 k-partials
        float g0 = xq0, g1 = xq1, g2 = xq2, g3 = xq3;
#pragma unroll
        for (int q = 0; q < 4; q++) {
            g0 += gxp[q * 1024 + bl * 128 + 0 * 32 + el2];
            g1 += gxp[q * 1024 + bl * 128 + 1 * 32 + el2];
            g2 += gxp[q * 1024 + bl * 128 + 2 * 32 + el2];
            g3 += gxp[q * 1024 + bl * 128 + 3 * 32 + el2];
        }
        float iv = fsig(g0);
        float fv = fsig(g1);
        float gv = ftanh(g2);
        float ov = fsig(g3);
        c_reg = fv * c_reg + iv * gv;
        float h = ov * ftanh(c_reg);
        int t_out = dir ? (TT - 1 - s) : s;
        g_seq[((size_t)b_e * TT + t_out) * 512 + dir * 256 + e] = h;

        if (s < TT - 1) {
            // push h into all 8 peers' hs[buf^1] at my slot
            uint32_t dst = slot[buf ^ 1];
#pragma unroll
            for (int r = 0; r < 8; r++) dsmem_st(dst, r, h);
            __syncthreads();            // all of this CTA's pushes issued
            if (tid < 8) {
                asm volatile("fence.acq_rel.cluster;" ::: "memory");
                mbar_arrive_cluster(mbar_a + 8u * (buf ^ 1), tid);
            }
        }
    }
}

// ---------------- kernel 4: LayerNorm + classifier + argmax ----------------
__global__ void ln_logits_kernel(const float* __restrict__ gamma, const float* __restrict__ beta,
                                 const float* __restrict__ cls_w, const float* __restrict__ cls_b,
                                 float* __restrict__ out, int out_size) {
    int tok = blockIdx.x;
    int tid = threadIdx.x;
    int lane = tid & 31;
    int warp = tid >> 5;

    float4 v = ((const float4*)(g_seq + (size_t)tok * 512))[tid];
    float s1 = v.x + v.y + v.z + v.w;
    float s2 = v.x * v.x + v.y * v.y + v.z * v.z + v.w * v.w;
#pragma unroll
    for (int off = 16; off; off >>= 1) {
        s1 += __shfl_down_sync(0xffffffffu, s1, off);
        s2 += __shfl_down_sync(0xffffffffu, s2, off);
    }
    __shared__ float a1[4], a2[4];
    __shared__ float mu_s, rstd_s;
    if (lane == 0) { a1[warp] = s1; a2[warp] = s2; }
    __syncthreads();
    if (tid == 0) {
        float t1 = a1[0] + a1[1] + a1[2] + a1[3];
        float t2 = a2[0] + a2[1] + a2[2] + a2[3];
        float mu = t1 * (1.0f / 512.0f);
        float var = t2 * (1.0f / 512.0f) - mu * mu;
        mu_s = mu;
        rstd_s = rsqrtf(var + 1e-5f);
    }
    __syncthreads();
    float mu = mu_s, rstd = rstd_s;

    float4 gm = ((const float4*)gamma)[tid];
    float4 bt = ((const float4*)beta)[tid];
    float4 y;
    y.x = (v.x - mu) * rstd * gm.x + bt.x;
    y.y = (v.y - mu) * rstd * gm.y + bt.y;
    y.z = (v.z - mu) * rstd * gm.z + bt.z;
    y.w = (v.w - mu) * rstd * gm.w + bt.w;

    float p[KK];
#pragma unroll
    for (int k = 0; k < KK; k++) {
        float4 w = ((const float4*)(cls_w + k * 512))[tid];
        p[k] = y.x * w.x + y.y * w.y + y.z * w.z + y.w * w.w;
    }
#pragma unroll
    for (int off = 16; off; off >>= 1) {
#pragma unroll
        for (int k = 0; k < KK; k++) p[k] += __shfl_down_sync(0xffffffffu, p[k], off);
    }
    __shared__ float wp[4][KK];
    __shared__ float lg[KK];
    if (lane == 0) {
#pragma unroll
        for (int k = 0; k < KK; k++) wp[warp][k] = p[k];
    }
    __syncthreads();
    if (tid < KK) {
        float l = wp[0][tid] + wp[1][tid] + wp[2][tid] + wp[3][tid] + cls_b[tid];
        g_logits[tok * KK + tid] = l;
        lg[tid] = l;
    }
    __syncthreads();
    if (tid == 0) {
        int am = 0;
        float bv = lg[0];
#pragma unroll
        for (int k = 1; k < KK; k++) { if (lg[k] > bv) { bv = lg[k]; am = k; } }
        if (1 + tok < out_size) out[1 + tok] = (float)am;
    }
}

// ---------------- kernel 5: CRF, one warp per batch ----------------
__global__ void crf_kernel(const int* __restrict__ label_ids, const float* __restrict__ crf_start,
                           const float* __restrict__ crf_end, const float* __restrict__ crf_trans) {
    int b = blockIdx.x;
    int lane = threadIdx.x;
    const unsigned FULL = 0xffffffffu;

    float num = 0.0f;
    for (int t = lane; t < TT; t += 32) {
        int tg = label_ids[b * TT + t];
        num += g_logits[(b * TT + t) * KK + tg];
        if (t < TT - 1) num += crf_trans[tg * KK + label_ids[b * TT + t + 1]];
    }
#pragma unroll
    for (int off = 16; off; off >>= 1) num += __shfl_down_sync(FULL, num, off);
    if (lane == 0) {
        num += crf_start[label_ids[b * TT]] + crf_end[label_ids[b * TT + TT - 1]];
    }

    bool act = lane < KK;
    float tcol[KK];
#pragma unroll
    for (int k = 0; k < KK; k++) tcol[k] = act ? crf_trans[k * KK + lane] : 0.0f;
    float alpha = act ? (crf_start[lane] + g_logits[(size_t)b * TT * KK + lane]) : -1e30f;

    for (int t = 1; t < TT; t++) {
        float em = act ? g_logits[((size_t)b * TT + t) * KK + lane] : 0.0f;
        float va[KK];
#pragma unroll
        for (int k = 0; k < KK; k++) va[k] = __shfl_sync(FULL, alpha, k) + tcol[k];
        float m = va[0];
#pragma unroll
        for (int k = 1; k < KK; k++) m = fmaxf(m, va[k]);
        float sme = 0.0f;
#pragma unroll
        for (int k = 0; k < KK; k++) sme += expf(va[k] - m);
        float na = em + m + logf(sme);
        alpha = act ? na : -1e30f;
    }

    float v = act ? (alpha + crf_end[lane]) : -1e30f;
    float m = v;
#pragma unroll
    for (int off = 16; off; off >>= 1) m = fmaxf(m, __shfl_xor_sync(FULL, m, off));
    float e = expf(v - m);
#pragma unroll
    for (int off = 16; off; off >>= 1) e += __shfl_xor_sync(FULL, e, off);
    float logZ = m + logf(e);

    if (lane == 0) g_llh[b] = num - logZ;
}

// ---------------- kernel 6: final loss reduction ----------------
__global__ void loss_kernel(float* __restrict__ out) {
    __shared__ float s[BB];
    int tid = threadIdx.x;
    s[tid] = g_llh[tid];
    __syncthreads();
    for (int off = 32; off; off >>= 1) {
        if (tid < off) s[tid] += s[tid + off];
        __syncthreads();
    }
    if (tid == 0) out[0] = -s[0];
}

// ---------------- launch ----------------
extern "C" void kernel_launch(void* const* d_in, const int* in_sizes, int n_in,
                              void* d_out, int out_size) {
    const int*   word_ids  = (const int*)d_in[0];
    const int*   label_ids = (const int*)d_in[1];
    const float* embed     = (const float*)d_in[2];
    const float* w_ih_f    = (const float*)d_in[3];
    const float* w_hh_f    = (const float*)d_in[4];
    const float* b_f       = (const float*)d_in[5];
    const float* w_ih_b    = (const float*)d_in[6];
    const float* w_hh_b    = (const float*)d_in[7];
    const float* b_b       = (const float*)d_in[8];
    const float* ln_gamma  = (const float*)d_in[9];
    const float* ln_beta   = (const float*)d_in[10];
    const float* cls_w     = (const float*)d_in[11];
    const float* cls_b     = (const float*)d_in[12];
    const float* crf_start = (const float*)d_in[13];
    const float* crf_end   = (const float*)d_in[14];
    const float* crf_trans = (const float*)d_in[15];
    float* out = (float*)d_out;

    const int PROJ_SMEM = (8192 + 32768) * 4;                  // 163840 B
    const int LSTM_SMEM = (32768 + 4096 + 4096) * 4 + 16;      // 163856 B
    cudaFuncSetAttribute(proj_kernel, cudaFuncAttributeMaxDynamicSharedMemorySize, PROJ_SMEM);
    cudaFuncSetAttribute(lstm_kernel, cudaFuncAttributeMaxDynamicSharedMemorySize, LSTM_SMEM);

    transpose_w_kernel<<<4096, 256>>>(w_ih_f, w_ih_b, w_hh_f, w_hh_b);
    proj_kernel<<<dim3(1024, 4, 2), 256, PROJ_SMEM>>>(word_ids, embed, b_f, b_b);
    lstm_kernel<<<dim3(64, 2), 256, LSTM_SMEM>>>();
    ln_logits_kernel<<<32768, 128>>>(ln_gamma, ln_beta, cls_w, cls_b, out, out_size);
    crf_kernel<<<BB, 32>>>(label_ids, crf_start, crf_end, crf_trans);
    loss_kernel<<<1, BB>>>(out);
}

// round 11
// speedup vs baseline: 1.3957x; 1.3957x over previous
#include <cuda_runtime.h>
#include <cstdint>

#define BB 64
#define TT 512
#define EE 256
#define H4 1024
#define KK 9

typedef unsigned long long ull;

// ---------------- device scratch (static) ----------------
// ih weights (idx 0,1): paired layout  float[((k>>1)*H4 + j)*2 + (k&1)]  == ull[k2*H4 + j]
// hh weights (idx 2,3): plain          float[k*H4 + j]
__device__ float g_wt[4][EE * H4];
__device__ float g_xp[2 * TT * BB * H4];       // [dir][step][b][j]
__device__ float g_seq[(size_t)BB * TT * 512]; // [b][t][2H]
__device__ float g_h[2][2][BB * EE];           // [dir][parity][b*E+e]
__device__ float g_logits[BB * TT * KK];
__device__ float g_llh[BB];
// per-(dir,bt)-group step flags: flag[grp*256 + et*32] = steps published (monotone in-run)
__device__ volatile int g_flag[16 * 256];
// init/terminal barrier (gen is monotone across replays; snapshot-compared -> replay-safe)
__device__ int g_bar_count[16 * 32];
__device__ int g_bar_gen[16 * 32];

__device__ __forceinline__ float fsig(float x) {
    return __fdividef(1.0f, 1.0f + __expf(-x));
}
__device__ __forceinline__ float ftanh(float x) {
    return __fdividef(2.0f, 1.0f + __expf(-2.0f * x)) - 1.0f;
}

__device__ __forceinline__ void fma2(ull& d, ull a, ull b) {
    asm("fma.rn.f32x2 %0, %1, %2, %0;" : "+l"(d) : "l"(a), "l"(b));
}
__device__ __forceinline__ float hsum2(ull v) {
    float lo, hi;
    asm("mov.b64 {%0,%1}, %2;" : "=f"(lo), "=f"(hi) : "l"(v));
    return lo + hi;
}

// ---------------- group barrier (init/terminal use only) ----------------
__device__ __forceinline__ void group_bar(int id, int n) {
    __syncthreads();
    if (threadIdx.x == 0) {
        int* cnt = &g_bar_count[id * 32];
        int* gen = &g_bar_gen[id * 32];
        int g0 = *(volatile int*)gen;
        __threadfence();
        int t = atomicAdd(cnt, 1);
        if (t == n - 1) {
            *cnt = 0;
            __threadfence();
            atomicAdd(gen, 1);
        } else {
            while (*(volatile int*)gen == g0) { __nanosleep(32); }
            __threadfence();
        }
    }
    __syncthreads();
}

// ---------------- kernel 1: weight transpose/pack ----------------
__global__ void transpose_w_kernel(const float* __restrict__ wf, const float* __restrict__ wb,
                                   const float* __restrict__ whf, const float* __restrict__ whb) {
    int idx = blockIdx.x * 256 + threadIdx.x;      // 4 * 262144 total
    int srcid = idx >> 18;
    int m = idx & 262143;
    int k = m >> 10;
    int j = m & 1023;
    const float* src = (srcid == 0) ? wf : (srcid == 1) ? wb : (srcid == 2) ? whf : whb;
    float v = src[j * EE + k];
    if (srcid < 2) g_wt[srcid][((k >> 1) * H4 + j) * 2 + (k & 1)] = v;   // paired over k
    else           g_wt[srcid][k * H4 + j] = v;                          // plain
}

// ---------------- kernel 2: embedding gather + input projections (f32x2) ----------------
__global__ void __launch_bounds__(256, 1) proj_kernel(const int* __restrict__ word_ids,
                                                      const float* __restrict__ embed,
                                                      const float* __restrict__ b_f,
                                                      const float* __restrict__ b_b) {
    extern __shared__ float psm[];
    float* esf = psm;                 // [32][256]   = 8192 floats
    ull*   wsm = (ull*)(psm + 8192);  // [64 k2][256 j] ull = 32768 floats
    __shared__ int wids[32];

    int dir = blockIdx.z;
    int jt  = blockIdx.y;             // j base jt*256
    int tile = blockIdx.x;
    int s  = tile >> 1;
    int b0 = (tile & 1) * 32;
    int t_src = dir ? (TT - 1 - s) : s;
    int tid = threadIdx.x;
    int jb = jt * 256;

    if (tid < 32) wids[tid] = word_ids[(b0 + tid) * TT + t_src];
    __syncthreads();
    for (int i = tid; i < 2048; i += 256) {
        int r = i >> 6, c = i & 63;
        ((float4*)&esf[r * 256])[c] = ((const float4*)(embed + (size_t)wids[r] * EE))[c];
    }

    int tg = tid >> 6;                // 0..3 -> tokens tg*8..tg*8+7
    int jq = tid & 63;                // -> j cols jb + jq*4 .. +3

    ull acc[8][4];
#pragma unroll
    for (int r = 0; r < 8; r++)
#pragma unroll
        for (int c = 0; c < 4; c++) acc[r][c] = 0ull;

    const float4* __restrict__ gw4 = (const float4*)g_wt[dir];

    for (int kc = 0; kc < 2; kc++) {
        __syncthreads();
        for (int i = tid; i < 8192; i += 256) {
            int k2l = i >> 7;
            int jj4 = i & 127;
            ((float4*)wsm)[i] = gw4[((size_t)((kc * 64 + k2l) * H4 + jb) >> 1) + jj4];
        }
        __syncthreads();

#pragma unroll 4
        for (int k2l = 0; k2l < 64; k2l += 2) {
            int kabs4 = kc * 128 + 2 * k2l;
            ulonglong2 a[8];
#pragma unroll
            for (int r = 0; r < 8; r++)
                a[r] = *(const ulonglong2*)&esf[(tg * 8 + r) * 256 + kabs4];
            const ull* wpA = &wsm[k2l * 256 + jq * 4];
            const ull* wpB = &wsm[(k2l + 1) * 256 + jq * 4];
            ulonglong2 wA01 = *(const ulonglong2*)wpA;
            ulonglong2 wA23 = *(const ulonglong2*)(wpA + 2);
            ulonglong2 wB01 = *(const ulonglong2*)wpB;
            ulonglong2 wB23 = *(const ulonglong2*)(wpB + 2);
#pragma unroll
            for (int r = 0; r < 8; r++) {
                fma2(acc[r][0], a[r].x, wA01.x);
                fma2(acc[r][1], a[r].x, wA01.y);
                fma2(acc[r][2], a[r].x, wA23.x);
                fma2(acc[r][3], a[r].x, wA23.y);
                fma2(acc[r][0], a[r].y, wB01.x);
                fma2(acc[r][1], a[r].y, wB01.y);
                fma2(acc[r][2], a[r].y, wB23.x);
                fma2(acc[r][3], a[r].y, wB23.y);
            }
        }
    }

    const float* bias_p = dir ? b_b : b_f;
    int j0 = jb + jq * 4;
    float4 bias = *(const float4*)&bias_p[j0];
    size_t base = ((size_t)dir * TT + s) * (BB * H4);
#pragma unroll
    for (int r = 0; r < 8; r++) {
        int b = b0 + tg * 8 + r;
        float4 v;
        v.x = hsum2(acc[r][0]) + bias.x;
        v.y = hsum2(acc[r][1]) + bias.y;
        v.z = hsum2(acc[r][2]) + bias.z;
        v.w = hsum2(acc[r][3]) + bias.w;
        *(float4*)&g_xp[base + (size_t)b * H4 + j0] = v;
    }
}

// ---------------- kernel 3: persistent BiLSTM, flag sync + direct-LDG h, f32x2 ----------------
// grid (64, 2), 256 threads. CTA (bt, et): 8 batch rows x 32 e-cols (all 4 gates local).
// Sync: per-step monotone flags (8 parallel volatile loads) instead of atomic ticket.
// h operands read directly from gmem (warp-uniform LDG; L1 after first touch) — no staging.
__global__ void __launch_bounds__(256, 1) lstm_kernel() {
    extern __shared__ float sm[];
    ull*   ws2 = (ull*)sm;            // [128 k2][128 col] ull  (131072 B)
    float* gxp = sm + 32768;          // [4 kh][8 row][128 col] (16384 B)

    int dir = blockIdx.y;
    int cta = blockIdx.x;
    int bt = cta >> 3;
    int et = cta & 7;
    int b_base = bt * 8;
    int grp = dir * 8 + bt;
    int tid = threadIdx.x;

    // GEMM thread mapping
    int jp = tid & 63;                // cols 2jp, 2jp+1  (col = g*32+el)
    int kh = tid >> 6;                // k2 in [kh*32, kh*32+32)

    // elementwise mapping
    int bl = tid >> 5;                // 0..7
    int el2 = tid & 31;
    int b_e = b_base + bl;
    int e = et * 32 + el2;

    // stage W_hh^T slice as k-pairs: ws2[k2*128 + col] = {w[2k2][C], w[2k2+1][C]}
    const float* __restrict__ whh_t = g_wt[2 + dir];
    float* wsf = sm;
    for (int i = tid; i < 32768; i += 256) {
        int k = i >> 7, col = i & 127;
        float v = whh_t[k * H4 + (col >> 5) * 256 + et * 32 + (col & 31)];
        wsf[((k >> 1) * 128 + col) * 2 + (k & 1)] = v;
    }
    // zero h buffer 0 (each CTA owns 256 contiguous elements)
    g_h[dir][0][cta * 256 + tid] = 0.0f;

    float c_reg = 0.0f;

    group_bar(grp, 8);   // h(0) + flags(=0 from init/reset) visible group-wide

    for (int s = 0; s < TT; s++) {
        int buf = s & 1;

        // prefetch xp into registers (overlaps the flag wait)
        const float* __restrict__ xpp = g_xp + ((size_t)dir * TT + s) * (BB * H4);
        float xq0 = xpp[(size_t)b_e * H4 + 0 * 256 + e];
        float xq1 = xpp[(size_t)b_e * H4 + 1 * 256 + e];
        float xq2 = xpp[(size_t)b_e * H4 + 2 * 256 + e];
        float xq3 = xpp[(size_t)b_e * H4 + 3 * 256 + e];

        if (s > 0) {
            if (tid < 32) {
                if (tid < 8) {
                    while (g_flag[grp * 256 + tid * 32] < s) { }
                }
                __threadfence();   // acquire (also invalidates L1 -> fresh h reads)
            }
            __syncthreads();
        }

        // GEMM: a (h) read directly from gmem, warp-uniform LDG.128 (2 k2 per load)
        const float* __restrict__ hsrc = &g_h[dir][buf][b_base * EE];
        ull acc[8][2];
#pragma unroll
        for (int r = 0; r < 8; r++) { acc[r][0] = 0ull; acc[r][1] = 0ull; }

        int k2b = kh * 32;
#pragma unroll 4
        for (int k2i = 0; k2i < 32; k2i += 2) {
            int k2 = k2b + k2i;
            ulonglong2 wA = *(const ulonglong2*)&ws2[k2 * 128 + 2 * jp];
            ulonglong2 wB = *(const ulonglong2*)&ws2[(k2 + 1) * 128 + 2 * jp];
#pragma unroll
            for (int r = 0; r < 8; r++) {
                ulonglong2 a = *(const ulonglong2*)&hsrc[r * 256 + 2 * k2];
                fma2(acc[r][0], a.x, wA.x);
                fma2(acc[r][1], a.x, wA.y);
                fma2(acc[r][0], a.y, wB.x);
                fma2(acc[r][1], a.y, wB.y);
            }
        }
        // write k-partials to exchange smem
#pragma unroll
        for (int r = 0; r < 8; r++) {
            float2 pv;
            pv.x = hsum2(acc[r][0]);
            pv.y = hsum2(acc[r][1]);
            *(float2*)&gxp[kh * 1024 + r * 128 + 2 * jp] = pv;
        }
        __syncthreads();

        // elementwise update (c in register), reduce 4 k-partials
        float g0 = xq0, g1 = xq1, g2 = xq2, g3 = xq3;
#pragma unroll
        for (int q = 0; q < 4; q++) {
            g0 += gxp[q * 1024 + bl * 128 + 0 * 32 + el2];
            g1 += gxp[q * 1024 + bl * 128 + 1 * 32 + el2];
            g2 += gxp[q * 1024 + bl * 128 + 2 * 32 + el2];
            g3 += gxp[q * 1024 + bl * 128 + 3 * 32 + el2];
        }
        float iv = fsig(g0);
        float fv = fsig(g1);
        float gv = ftanh(g2);
        float ov = fsig(g3);
        c_reg = fv * c_reg + iv * gv;
        float h = ov * ftanh(c_reg);
        g_h[dir][buf ^ 1][b_e * EE + e] = h;
        int t_out = dir ? (TT - 1 - s) : s;
        g_seq[((size_t)b_e * TT + t_out) * 512 + dir * 256 + e] = h;

        if (s < TT - 1) {
            __syncthreads();                 // all h stores issued (CTA-ordered by bar)
            if (tid == 0) {
                __threadfence();             // release: h visible at gpu scope
                g_flag[grp * 256 + et * 32] = s + 1;
            }
        }
    }

    // terminal barrier, then reset flags for the next graph replay
    group_bar(grp, 8);
    if (tid == 0) g_flag[grp * 256 + et * 32] = 0;
}

// ---------------- kernel 4: LayerNorm + classifier + argmax ----------------
__global__ void ln_logits_kernel(const float* __restrict__ gamma, const float* __restrict__ beta,
                                 const float* __restrict__ cls_w, const float* __restrict__ cls_b,
                                 float* __restrict__ out, int out_size) {
    int tok = blockIdx.x;
    int tid = threadIdx.x;
    int lane = tid & 31;
    int warp = tid >> 5;

    float4 v = ((const float4*)(g_seq + (size_t)tok * 512))[tid];
    float s1 = v.x + v.y + v.z + v.w;
    float s2 = v.x * v.x + v.y * v.y + v.z * v.z + v.w * v.w;
#pragma unroll
    for (int off = 16; off; off >>= 1) {
        s1 += __shfl_down_sync(0xffffffffu, s1, off);
        s2 += __shfl_down_sync(0xffffffffu, s2, off);
    }
    __shared__ float a1[4], a2[4];
    __shared__ float mu_s, rstd_s;
    if (lane == 0) { a1[warp] = s1; a2[warp] = s2; }
    __syncthreads();
    if (tid == 0) {
        float t1 = a1[0] + a1[1] + a1[2] + a1[3];
        float t2 = a2[0] + a2[1] + a2[2] + a2[3];
        float mu = t1 * (1.0f / 512.0f);
        float var = t2 * (1.0f / 512.0f) - mu * mu;
        mu_s = mu;
        rstd_s = rsqrtf(var + 1e-5f);
    }
    __syncthreads();
    float mu = mu_s, rstd = rstd_s;

    float4 gm = ((const float4*)gamma)[tid];
    float4 bt = ((const float4*)beta)[tid];
    float4 y;
    y.x = (v.x - mu) * rstd * gm.x + bt.x;
    y.y = (v.y - mu) * rstd * gm.y + bt.y;
    y.z = (v.z - mu) * rstd * gm.z + bt.z;
    y.w = (v.w - mu) * rstd * gm.w + bt.w;

    float p[KK];
#pragma unroll
    for (int k = 0; k < KK; k++) {
        float4 w = ((const float4*)(cls_w + k * 512))[tid];
        p[k] = y.x * w.x + y.y * w.y + y.z * w.z + y.w * w.w;
    }
#pragma unroll
    for (int off = 16; off; off >>= 1) {
#pragma unroll
        for (int k = 0; k < KK; k++) p[k] += __shfl_down_sync(0xffffffffu, p[k], off);
    }
    __shared__ float wp[4][KK];
    __shared__ float lg[KK];
    if (lane == 0) {
#pragma unroll
        for (int k = 0; k < KK; k++) wp[warp][k] = p[k];
    }
    __syncthreads();
    if (tid < KK) {
        float l = wp[0][tid] + wp[1][tid] + wp[2][tid] + wp[3][tid] + cls_b[tid];
        g_logits[tok * KK + tid] = l;
        lg[tid] = l;
    }
    __syncthreads();
    if (tid == 0) {
        int am = 0;
        float bv = lg[0];
#pragma unroll
        for (int k = 1; k < KK; k++) { if (lg[k] > bv) { bv = lg[k]; am = k; } }
        if (1 + tok < out_size) out[1 + tok] = (float)am;
    }
}

// ---------------- kernel 5: CRF, one warp per batch ----------------
__global__ void crf_kernel(const int* __restrict__ label_ids, const float* __restrict__ crf_start,
                           const float* __restrict__ crf_end, const float* __restrict__ crf_trans) {
    int b = blockIdx.x;
    int lane = threadIdx.x;
    const unsigned FULL = 0xffffffffu;

    float num = 0.0f;
    for (int t = lane; t < TT; t += 32) {
        int tg = label_ids[b * TT + t];
        num += g_logits[(b * TT + t) * KK + tg];
        if (t < TT - 1) num += crf_trans[tg * KK + label_ids[b * TT + t + 1]];
    }
#pragma unroll
    for (int off = 16; off; off >>= 1) num += __shfl_down_sync(FULL, num, off);
    if (lane == 0) {
        num += crf_start[label_ids[b * TT]] + crf_end[label_ids[b * TT + TT - 1]];
    }

    bool act = lane < KK;
    float tcol[KK];
#pragma unroll
    for (int k = 0; k < KK; k++) tcol[k] = act ? crf_trans[k * KK + lane] : 0.0f;
    float alpha = act ? (crf_start[lane] + g_logits[(size_t)b * TT * KK + lane]) : -1e30f;

    for (int t = 1; t < TT; t++) {
        float em = act ? g_logits[((size_t)b * TT + t) * KK + lane] : 0.0f;
        float va[KK];
#pragma unroll
        for (int k = 0; k < KK; k++) va[k] = __shfl_sync(FULL, alpha, k) + tcol[k];
        float m = va[0];
#pragma unroll
        for (int k = 1; k < KK; k++) m = fmaxf(m, va[k]);
        float sme = 0.0f;
#pragma unroll
        for (int k = 0; k < KK; k++) sme += expf(va[k] - m);
        float na = em + m + logf(sme);
        alpha = act ? na : -1e30f;
    }

    float v = act ? (alpha + crf_end[lane]) : -1e30f;
    float m = v;
#pragma unroll
    for (int off = 16; off; off >>= 1) m = fmaxf(m, __shfl_xor_sync(FULL, m, off));
    float e = expf(v - m);
#pragma unroll
    for (int off = 16; off; off >>= 1) e += __shfl_xor_sync(FULL, e, off);
    float logZ = m + logf(e);

    if (lane == 0) g_llh[b] = num - logZ;
}

// ---------------- kernel 6: final loss reduction ----------------
__global__ void loss_kernel(float* __restrict__ out) {
    __shared__ float s[BB];
    int tid = threadIdx.x;
    s[tid] = g_llh[tid];
    __syncthreads();
    for (int off = 32; off; off >>= 1) {
        if (tid < off) s[tid] += s[tid + off];
        __syncthreads();
    }
    if (tid == 0) out[0] = -s[0];
}

// ---------------- launch ----------------
extern "C" void kernel_launch(void* const* d_in, const int* in_sizes, int n_in,
                              void* d_out, int out_size) {
    const int*   word_ids  = (const int*)d_in[0];
    const int*   label_ids = (const int*)d_in[1];
    const float* embed     = (const float*)d_in[2];
    const float* w_ih_f    = (const float*)d_in[3];
    const float* w_hh_f    = (const float*)d_in[4];
    const float* b_f       = (const float*)d_in[5];
    const float* w_ih_b    = (const float*)d_in[6];
    const float* w_hh_b    = (const float*)d_in[7];
    const float* b_b       = (const float*)d_in[8];
    const float* ln_gamma  = (const float*)d_in[9];
    const float* ln_beta   = (const float*)d_in[10];
    const float* cls_w     = (const float*)d_in[11];
    const float* cls_b     = (const float*)d_in[12];
    const float* crf_start = (const float*)d_in[13];
    const float* crf_end   = (const float*)d_in[14];
    const float* crf_trans = (const float*)d_in[15];
    float* out = (float*)d_out;

    const int PROJ_SMEM = (8192 + 32768) * 4;           // 163840 B
    const int LSTM_SMEM = (32768 + 4096) * 4;           // 147456 B
    cudaFuncSetAttribute(proj_kernel, cudaFuncAttributeMaxDynamicSharedMemorySize, PROJ_SMEM);
    cudaFuncSetAttribute(lstm_kernel, cudaFuncAttributeMaxDynamicSharedMemorySize, LSTM_SMEM);

    transpose_w_kernel<<<4096, 256>>>(w_ih_f, w_ih_b, w_hh_f, w_hh_b);
    proj_kernel<<<dim3(1024, 4, 2), 256, PROJ_SMEM>>>(word_ids, embed, b_f, b_b);
    lstm_kernel<<<dim3(64, 2), 256, LSTM_SMEM>>>();
    ln_logits_kernel<<<32768, 128>>>(ln_gamma, ln_beta, cls_w, cls_b, out, out_size);
    crf_kernel<<<BB, 32>>>(label_ids, crf_start, crf_end, crf_trans);
    loss_kernel<<<1, BB>>>(out);
}

// round 12
// speedup vs baseline: 1.7276x; 1.2378x over previous
#include <cuda_runtime.h>
#include <cstdint>

#define BB 64
#define TT 512
#define EE 256
#define H4 1024
#define KK 9

typedef unsigned long long ull;

// ---------------- device scratch (static) ----------------
// ih weights (idx 0,1): paired layout  float[((k>>1)*H4 + j)*2 + (k&1)]  == ull[k2*H4 + j]
// hh weights (idx 2,3): plain          float[k*H4 + j]
__device__ float g_wt[4][EE * H4];
__device__ float g_xp[2 * TT * BB * H4];       // [dir][step][b][j]
__device__ float g_seq[(size_t)BB * TT * 512]; // [b][t][2H]
__device__ float g_h[2][2][BB * EE];           // [dir][parity][b*E+e]
__device__ float g_logits[BB * TT * KK];
__device__ float g_llh[BB];
// per-(dir,bt)-group step flags: flag[grp*256 + et*32] = steps published (monotone in-run)
__device__ int g_flag[16 * 256];
// init/terminal barrier (gen snapshot-compared -> replay-safe)
__device__ int g_bar_count[16 * 32];
__device__ int g_bar_gen[16 * 32];

__device__ __forceinline__ float fsig(float x) {
    return __fdividef(1.0f, 1.0f + __expf(-x));
}
__device__ __forceinline__ float ftanh(float x) {
    return __fdividef(2.0f, 1.0f + __expf(-2.0f * x)) - 1.0f;
}

__device__ __forceinline__ void fma2(ull& d, ull a, ull b) {
    asm("fma.rn.f32x2 %0, %1, %2, %0;" : "+l"(d) : "l"(a), "l"(b));
}
__device__ __forceinline__ float hsum2(ull v) {
    float lo, hi;
    asm("mov.b64 {%0,%1}, %2;" : "=f"(lo), "=f"(hi) : "l"(v));
    return lo + hi;
}

// strong-GPU flag ops: no fence instruction, no CCTL.IVALL (L1 untouched)
__device__ __forceinline__ int ld_acq(const int* p) {
    int v;
    asm volatile("ld.acquire.gpu.global.b32 %0, [%1];" : "=r"(v) : "l"(p) : "memory");
    return v;
}
__device__ __forceinline__ void st_rel(int* p, int v) {
    asm volatile("st.release.gpu.global.b32 [%0], %1;" :: "l"(p), "r"(v) : "memory");
}

// ---------------- group barrier (init/terminal use only) ----------------
__device__ __forceinline__ void group_bar(int id, int n) {
    __syncthreads();
    if (threadIdx.x == 0) {
        int* cnt = &g_bar_count[id * 32];
        int* gen = &g_bar_gen[id * 32];
        int g0 = *(volatile int*)gen;
        __threadfence();
        int t = atomicAdd(cnt, 1);
        if (t == n - 1) {
            *cnt = 0;
            __threadfence();
            atomicAdd(gen, 1);
        } else {
            while (*(volatile int*)gen == g0) { __nanosleep(32); }
            __threadfence();
        }
    }
    __syncthreads();
}

// ---------------- kernel 1: weight transpose/pack ----------------
__global__ void transpose_w_kernel(const float* __restrict__ wf, const float* __restrict__ wb,
                                   const float* __restrict__ whf, const float* __restrict__ whb) {
    int idx = blockIdx.x * 256 + threadIdx.x;      // 4 * 262144 total
    int srcid = idx >> 18;
    int m = idx & 262143;
    int k = m >> 10;
    int j = m & 1023;
    const float* src = (srcid == 0) ? wf : (srcid == 1) ? wb : (srcid == 2) ? whf : whb;
    float v = src[j * EE + k];
    if (srcid < 2) g_wt[srcid][((k >> 1) * H4 + j) * 2 + (k & 1)] = v;   // paired over k
    else           g_wt[srcid][k * H4 + j] = v;                          // plain
}

// ---------------- kernel 2: embedding gather + input projections (f32x2) ----------------
__global__ void __launch_bounds__(256, 1) proj_kernel(const int* __restrict__ word_ids,
                                                      const float* __restrict__ embed,
                                                      const float* __restrict__ b_f,
                                                      const float* __restrict__ b_b) {
    extern __shared__ float psm[];
    float* esf = psm;                 // [32][256]   = 8192 floats
    ull*   wsm = (ull*)(psm + 8192);  // [64 k2][256 j] ull = 32768 floats
    __shared__ int wids[32];

    int dir = blockIdx.z;
    int jt  = blockIdx.y;             // j base jt*256
    int tile = blockIdx.x;
    int s  = tile >> 1;
    int b0 = (tile & 1) * 32;
    int t_src = dir ? (TT - 1 - s) : s;
    int tid = threadIdx.x;
    int jb = jt * 256;

    if (tid < 32) wids[tid] = word_ids[(b0 + tid) * TT + t_src];
    __syncthreads();
    for (int i = tid; i < 2048; i += 256) {
        int r = i >> 6, c = i & 63;
        ((float4*)&esf[r * 256])[c] = ((const float4*)(embed + (size_t)wids[r] * EE))[c];
    }

    int tg = tid >> 6;                // 0..3 -> tokens tg*8..tg*8+7
    int jq = tid & 63;                // -> j cols jb + jq*4 .. +3

    ull acc[8][4];
#pragma unroll
    for (int r = 0; r < 8; r++)
#pragma unroll
        for (int c = 0; c < 4; c++) acc[r][c] = 0ull;

    const float4* __restrict__ gw4 = (const float4*)g_wt[dir];

    for (int kc = 0; kc < 2; kc++) {
        __syncthreads();
        for (int i = tid; i < 8192; i += 256) {
            int k2l = i >> 7;
            int jj4 = i & 127;
            ((float4*)wsm)[i] = gw4[((size_t)((kc * 64 + k2l) * H4 + jb) >> 1) + jj4];
        }
        __syncthreads();

#pragma unroll 4
        for (int k2l = 0; k2l < 64; k2l += 2) {
            int kabs4 = kc * 128 + 2 * k2l;
            ulonglong2 a[8];
#pragma unroll
            for (int r = 0; r < 8; r++)
                a[r] = *(const ulonglong2*)&esf[(tg * 8 + r) * 256 + kabs4];
            const ull* wpA = &wsm[k2l * 256 + jq * 4];
            const ull* wpB = &wsm[(k2l + 1) * 256 + jq * 4];
            ulonglong2 wA01 = *(const ulonglong2*)wpA;
            ulonglong2 wA23 = *(const ulonglong2*)(wpA + 2);
            ulonglong2 wB01 = *(const ulonglong2*)wpB;
            ulonglong2 wB23 = *(const ulonglong2*)(wpB + 2);
#pragma unroll
            for (int r = 0; r < 8; r++) {
                fma2(acc[r][0], a[r].x, wA01.x);
                fma2(acc[r][1], a[r].x, wA01.y);
                fma2(acc[r][2], a[r].x, wA23.x);
                fma2(acc[r][3], a[r].x, wA23.y);
                fma2(acc[r][0], a[r].y, wB01.x);
                fma2(acc[r][1], a[r].y, wB01.y);
                fma2(acc[r][2], a[r].y, wB23.x);
                fma2(acc[r][3], a[r].y, wB23.y);
            }
        }
    }

    const float* bias_p = dir ? b_b : b_f;
    int j0 = jb + jq * 4;
    float4 bias = *(const float4*)&bias_p[j0];
    size_t base = ((size_t)dir * TT + s) * (BB * H4);
#pragma unroll
    for (int r = 0; r < 8; r++) {
        int b = b0 + tg * 8 + r;
        float4 v;
        v.x = hsum2(acc[r][0]) + bias.x;
        v.y = hsum2(acc[r][1]) + bias.y;
        v.z = hsum2(acc[r][2]) + bias.z;
        v.w = hsum2(acc[r][3]) + bias.w;
        *(float4*)&g_xp[base + (size_t)b * H4 + j0] = v;
    }
}

// ---------------- kernel 3: persistent BiLSTM, release/acquire sync, f32x2 ----------------
// grid (64, 2), 256 threads. CTA (bt, et): 8 batch rows x 32 e-cols (all 4 gates local).
// Sync per step: producer {__stcg h; bar; tid0 st.release.gpu flag}; consumer {8 threads
// poll flags with ld.acquire.gpu; bar; stage h via __ldcg}. No fences -> no L1D flush.
__global__ void __launch_bounds__(256, 1) lstm_kernel() {
    extern __shared__ float sm[];
    ull*   ws2 = (ull*)sm;            // [128 k2][128 col] ull  (131072 B)
    float* hs  = sm + 32768;          // [8][256]               (8192 B)
    float* gxp = sm + 32768 + 2048;   // [4 kh][8 row][128 col] (16384 B)

    int dir = blockIdx.y;
    int cta = blockIdx.x;
    int bt = cta >> 3;
    int et = cta & 7;
    int b_base = bt * 8;
    int grp = dir * 8 + bt;
    int tid = threadIdx.x;

    // GEMM thread mapping
    int jp = tid & 63;                // cols 2jp, 2jp+1  (col = g*32+el)
    int kh = tid >> 6;                // k2 in [kh*32, kh*32+32)

    // elementwise mapping
    int bl = tid >> 5;                // 0..7
    int el2 = tid & 31;
    int b_e = b_base + bl;
    int e = et * 32 + el2;

    // stage W_hh^T slice as k-pairs: ws2[k2*128 + col] = {w[2k2][C], w[2k2+1][C]}
    const float* __restrict__ whh_t = g_wt[2 + dir];
    float* wsf = sm;
    for (int i = tid; i < 32768; i += 256) {
        int k = i >> 7, col = i & 127;
        float v = whh_t[k * H4 + (col >> 5) * 256 + et * 32 + (col & 31)];
        wsf[((k >> 1) * 128 + col) * 2 + (k & 1)] = v;
    }
    // zero h buffer 0 (each CTA owns 256 contiguous elements); L2-direct
    __stcg(&g_h[dir][0][cta * 256 + tid], 0.0f);

    float c_reg = 0.0f;

    group_bar(grp, 8);   // h(0) + flags(=0 from init/reset) visible group-wide

    for (int s = 0; s < TT; s++) {
        int buf = s & 1;

        // prefetch xp into registers (L1-resident stream; overlaps the flag wait)
        const float* __restrict__ xpp = g_xp + ((size_t)dir * TT + s) * (BB * H4);
        float xq0 = xpp[(size_t)b_e * H4 + 0 * 256 + e];
        float xq1 = xpp[(size_t)b_e * H4 + 1 * 256 + e];
        float xq2 = xpp[(size_t)b_e * H4 + 2 * 256 + e];
        float xq3 = xpp[(size_t)b_e * H4 + 3 * 256 + e];

        if (s > 0) {
            if (tid < 8) {
                while (ld_acq(&g_flag[grp * 256 + tid * 32]) < s) { }
            }
            __syncthreads();
        }

        // stage h tile [8][256] via L2-direct loads (no L1 staleness possible)
        {
            const float4* src = (const float4*)&g_h[dir][buf][b_base * EE];
            float4* dst = (float4*)hs;
            dst[tid] = __ldcg(src + tid);
            dst[tid + 256] = __ldcg(src + tid + 256);
        }
        __syncthreads();

        // GEMM: this thread's k-slice, 2 cols, all 8 rows; 2 k2 per iter
        ull acc[8][2];
#pragma unroll
        for (int r = 0; r < 8; r++) { acc[r][0] = 0ull; acc[r][1] = 0ull; }

        int k2b = kh * 32;
#pragma unroll 4
        for (int k2i = 0; k2i < 32; k2i += 2) {
            int k2 = k2b + k2i;
            ulonglong2 wA = *(const ulonglong2*)&ws2[k2 * 128 + 2 * jp];
            ulonglong2 wB = *(const ulonglong2*)&ws2[(k2 + 1) * 128 + 2 * jp];
#pragma unroll
            for (int r = 0; r < 8; r++) {
                ulonglong2 a = *(const ulonglong2*)&hs[r * 256 + 2 * k2];
                fma2(acc[r][0], a.x, wA.x);
                fma2(acc[r][1], a.x, wA.y);
                fma2(acc[r][0], a.y, wB.x);
                fma2(acc[r][1], a.y, wB.y);
            }
        }
        // write k-partials to exchange smem
#pragma unroll
        for (int r = 0; r < 8; r++) {
            float2 pv;
            pv.x = hsum2(acc[r][0]);
            pv.y = hsum2(acc[r][1]);
            *(float2*)&gxp[kh * 1024 + r * 128 + 2 * jp] = pv;
        }
        __syncthreads();

        // elementwise update (c in register), reduce 4 k-partials
        float g0 = xq0, g1 = xq1, g2 = xq2, g3 = xq3;
#pragma unroll
        for (int q = 0; q < 4; q++) {
            g0 += gxp[q * 1024 + bl * 128 + 0 * 32 + el2];
            g1 += gxp[q * 1024 + bl * 128 + 1 * 32 + el2];
            g2 += gxp[q * 1024 + bl * 128 + 2 * 32 + el2];
            g3 += gxp[q * 1024 + bl * 128 + 3 * 32 + el2];
        }
        float iv = fsig(g0);
        float fv = fsig(g1);
        float gv = ftanh(g2);
        float ov = fsig(g3);
        c_reg = fv * c_reg + iv * gv;
        float h = ov * ftanh(c_reg);
        __stcg(&g_h[dir][buf ^ 1][b_e * EE + e], h);       // L2-direct publish
        int t_out = dir ? (TT - 1 - s) : s;
        __stcg(&g_seq[((size_t)b_e * TT + t_out) * 512 + dir * 256 + e], h);

        if (s < TT - 1) {
            __syncthreads();                               // all h stores before release
            if (tid == 0) st_rel(&g_flag[grp * 256 + et * 32], s + 1);
        }
    }

    // terminal barrier, then reset flags for the next graph replay
    group_bar(grp, 8);
    if (tid == 0) g_flag[grp * 256 + et * 32] = 0;
}

// ---------------- kernel 4: LayerNorm + classifier + argmax ----------------
__global__ void ln_logits_kernel(const float* __restrict__ gamma, const float* __restrict__ beta,
                                 const float* __restrict__ cls_w, const float* __restrict__ cls_b,
                                 float* __restrict__ out, int out_size) {
    int tok = blockIdx.x;
    int tid = threadIdx.x;
    int lane = tid & 31;
    int warp = tid >> 5;

    float4 v = ((const float4*)(g_seq + (size_t)tok * 512))[tid];
    float s1 = v.x + v.y + v.z + v.w;
    float s2 = v.x * v.x + v.y * v.y + v.z * v.z + v.w * v.w;
#pragma unroll
    for (int off = 16; off; off >>= 1) {
        s1 += __shfl_down_sync(0xffffffffu, s1, off);
        s2 += __shfl_down_sync(0xffffffffu, s2, off);
    }
    __shared__ float a1[4], a2[4];
    __shared__ float mu_s, rstd_s;
    if (lane == 0) { a1[warp] = s1; a2[warp] = s2; }
    __syncthreads();
    if (tid == 0) {
        float t1 = a1[0] + a1[1] + a1[2] + a1[3];
        float t2 = a2[0] + a2[1] + a2[2] + a2[3];
        float mu = t1 * (1.0f / 512.0f);
        float var = t2 * (1.0f / 512.0f) - mu * mu;
        mu_s = mu;
        rstd_s = rsqrtf(var + 1e-5f);
    }
    __syncthreads();
    float mu = mu_s, rstd = rstd_s;

    float4 gm = ((const float4*)gamma)[tid];
    float4 bt = ((const float4*)beta)[tid];
    float4 y;
    y.x = (v.x - mu) * rstd * gm.x + bt.x;
    y.y = (v.y - mu) * rstd * gm.y + bt.y;
    y.z = (v.z - mu) * rstd * gm.z + bt.z;
    y.w = (v.w - mu) * rstd * gm.w + bt.w;

    float p[KK];
#pragma unroll
    for (int k = 0; k < KK; k++) {
        float4 w = ((const float4*)(cls_w + k * 512))[tid];
        p[k] = y.x * w.x + y.y * w.y + y.z * w.z + y.w * w.w;
    }
#pragma unroll
    for (int off = 16; off; off >>= 1) {
#pragma unroll
        for (int k = 0; k < KK; k++) p[k] += __shfl_down_sync(0xffffffffu, p[k], off);
    }
    __shared__ float wp[4][KK];
    __shared__ float lg[KK];
    if (lane == 0) {
#pragma unroll
        for (int k = 0; k < KK; k++) wp[warp][k] = p[k];
    }
    __syncthreads();
    if (tid < KK) {
        float l = wp[0][tid] + wp[1][tid] + wp[2][tid] + wp[3][tid] + cls_b[tid];
        g_logits[tok * KK + tid] = l;
        lg[tid] = l;
    }
    __syncthreads();
    if (tid == 0) {
        int am = 0;
        float bv = lg[0];
#pragma unroll
        for (int k = 1; k < KK; k++) { if (lg[k] > bv) { bv = lg[k]; am = k; } }
        if (1 + tok < out_size) out[1 + tok] = (float)am;
    }
}

// ---------------- kernel 5: CRF, one warp per batch ----------------
__global__ void crf_kernel(const int* __restrict__ label_ids, const float* __restrict__ crf_start,
                           const float* __restrict__ crf_end, const float* __restrict__ crf_trans) {
    int b = blockIdx.x;
    int lane = threadIdx.x;
    const unsigned FULL = 0xffffffffu;

    float num = 0.0f;
    for (int t = lane; t < TT; t += 32) {
        int tg = label_ids[b * TT + t];
        num += g_logits[(b * TT + t) * KK + tg];
        if (t < TT - 1) num += crf_trans[tg * KK + label_ids[b * TT + t + 1]];
    }
#pragma unroll
    for (int off = 16; off; off >>= 1) num += __shfl_down_sync(FULL, num, off);
    if (lane == 0) {
        num += crf_start[label_ids[b * TT]] + crf_end[label_ids[b * TT + TT - 1]];
    }

    bool act = lane < KK;
    float tcol[KK];
#pragma unroll
    for (int k = 0; k < KK; k++) tcol[k] = act ? crf_trans[k * KK + lane] : 0.0f;
    float alpha = act ? (crf_start[lane] + g_logits[(size_t)b * TT * KK + lane]) : -1e30f;

    for (int t = 1; t < TT; t++) {
        float em = act ? g_logits[((size_t)b * TT + t) * KK + lane] : 0.0f;
        float va[KK];
#pragma unroll
        for (int k = 0; k < KK; k++) va[k] = __shfl_sync(FULL, alpha, k) + tcol[k];
        float m = va[0];
#pragma unroll
        for (int k = 1; k < KK; k++) m = fmaxf(m, va[k]);
        float sme = 0.0f;
#pragma unroll
        for (int k = 0; k < KK; k++) sme += expf(va[k] - m);
        float na = em + m + logf(sme);
        alpha = act ? na : -1e30f;
    }

    float v = act ? (alpha + crf_end[lane]) : -1e30f;
    float m = v;
#pragma unroll
    for (int off = 16; off; off >>= 1) m = fmaxf(m, __shfl_xor_sync(FULL, m, off));
    float e = expf(v - m);
#pragma unroll
    for (int off = 16; off; off >>= 1) e += __shfl_xor_sync(FULL, e, off);
    float logZ = m + logf(e);

    if (lane == 0) g_llh[b] = num - logZ;
}

// ---------------- kernel 6: final loss reduction ----------------
__global__ void loss_kernel(float* __restrict__ out) {
    __shared__ float s[BB];
    int tid = threadIdx.x;
    s[tid] = g_llh[tid];
    __syncthreads();
    for (int off = 32; off; off >>= 1) {
        if (tid < off) s[tid] += s[tid + off];
        __syncthreads();
    }
    if (tid == 0) out[0] = -s[0];
}

// ---------------- launch ----------------
extern "C" void kernel_launch(void* const* d_in, const int* in_sizes, int n_in,
                              void* d_out, int out_size) {
    const int*   word_ids  = (const int*)d_in[0];
    const int*   label_ids = (const int*)d_in[1];
    const float* embed     = (const float*)d_in[2];
    const float* w_ih_f    = (const float*)d_in[3];
    const float* w_hh_f    = (const float*)d_in[4];
    const float* b_f       = (const float*)d_in[5];
    const float* w_ih_b    = (const float*)d_in[6];
    const float* w_hh_b    = (const float*)d_in[7];
    const float* b_b       = (const float*)d_in[8];
    const float* ln_gamma  = (const float*)d_in[9];
    const float* ln_beta   = (const float*)d_in[10];
    const float* cls_w     = (const float*)d_in[11];
    const float* cls_b     = (const float*)d_in[12];
    const float* crf_start = (const float*)d_in[13];
    const float* crf_end   = (const float*)d_in[14];
    const float* crf_trans = (const float*)d_in[15];
    float* out = (float*)d_out;

    const int PROJ_SMEM = (8192 + 32768) * 4;           // 163840 B
    const int LSTM_SMEM = (32768 + 2048 + 4096) * 4;    // 155648 B
    cudaFuncSetAttribute(proj_kernel, cudaFuncAttributeMaxDynamicSharedMemorySize, PROJ_SMEM);
    cudaFuncSetAttribute(lstm_kernel, cudaFuncAttributeMaxDynamicSharedMemorySize, LSTM_SMEM);

    transpose_w_kernel<<<4096, 256>>>(w_ih_f, w_ih_b, w_hh_f, w_hh_b);
    proj_kernel<<<dim3(1024, 4, 2), 256, PROJ_SMEM>>>(word_ids, embed, b_f, b_b);
    lstm_kernel<<<dim3(64, 2), 256, LSTM_SMEM>>>();
    ln_logits_kernel<<<32768, 128>>>(ln_gamma, ln_beta, cls_w, cls_b, out, out_size);
    crf_kernel<<<BB, 32>>>(label_ids, crf_start, crf_end, crf_trans);
    loss_kernel<<<1, BB>>>(out);
}

// round 13
// speedup vs baseline: 1.7718x; 1.0256x over previous
#include <cuda_runtime.h>
#include <cstdint>

#define BB 64
#define TT 512
#define EE 256
#define H4 1024
#define KK 9

typedef unsigned long long ull;

// ---------------- device scratch (static) ----------------
// ih weights (idx 0,1): paired layout  float[((k>>1)*H4 + j)*2 + (k&1)]  == ull[k2*H4 + j]
// hh weights (idx 2,3): plain          float[k*H4 + j]
__device__ float g_wt[4][EE * H4];
__device__ float g_xp[2 * TT * BB * H4];       // [dir][step][b][j]
__device__ float g_seq[(size_t)BB * TT * 512]; // [b][t][2H]
__device__ float g_h[2][2][BB * EE];           // [dir][parity][b*E+e]
__device__ float g_logits[BB * TT * KK];
__device__ float g_llh[BB];
// per-(dir,bt)-group step flags: flag[grp*256 + et*32] = steps published (monotone in-run)
__device__ int g_flag[16 * 256];
// init/terminal barrier (gen snapshot-compared -> replay-safe)
__device__ int g_bar_count[16 * 32];
__device__ int g_bar_gen[16 * 32];

__device__ __forceinline__ float fsig(float x) {
    return __fdividef(1.0f, 1.0f + __expf(-x));
}
__device__ __forceinline__ float ftanh(float x) {
    return __fdividef(2.0f, 1.0f + __expf(-2.0f * x)) - 1.0f;
}

__device__ __forceinline__ void fma2(ull& d, ull a, ull b) {
    asm("fma.rn.f32x2 %0, %1, %2, %0;" : "+l"(d) : "l"(a), "l"(b));
}
__device__ __forceinline__ float hsum2(ull v) {
    float lo, hi;
    asm("mov.b64 {%0,%1}, %2;" : "=f"(lo), "=f"(hi) : "l"(v));
    return lo + hi;
}

// strong-GPU flag ops: no fence instruction, no CCTL.IVALL (L1 untouched)
__device__ __forceinline__ int ld_acq(const int* p) {
    int v;
    asm volatile("ld.acquire.gpu.global.b32 %0, [%1];" : "=r"(v) : "l"(p) : "memory");
    return v;
}
__device__ __forceinline__ void st_rel(int* p, int v) {
    asm volatile("st.release.gpu.global.b32 [%0], %1;" :: "l"(p), "r"(v) : "memory");
}
__device__ __forceinline__ void named_bar(int id, int cnt) {
    asm volatile("bar.sync %0, %1;" :: "r"(id), "r"(cnt) : "memory");
}

// ---------------- group barrier (init/terminal use only) ----------------
__device__ __forceinline__ void group_bar(int id, int n) {
    __syncthreads();
    if (threadIdx.x == 0) {
        int* cnt = &g_bar_count[id * 32];
        int* gen = &g_bar_gen[id * 32];
        int g0 = *(volatile int*)gen;
        __threadfence();
        int t = atomicAdd(cnt, 1);
        if (t == n - 1) {
            *cnt = 0;
            __threadfence();
            atomicAdd(gen, 1);
        } else {
            while (*(volatile int*)gen == g0) { __nanosleep(32); }
            __threadfence();
        }
    }
    __syncthreads();
}

// ---------------- kernel 1: weight transpose/pack ----------------
__global__ void transpose_w_kernel(const float* __restrict__ wf, const float* __restrict__ wb,
                                   const float* __restrict__ whf, const float* __restrict__ whb) {
    int idx = blockIdx.x * 256 + threadIdx.x;      // 4 * 262144 total
    int srcid = idx >> 18;
    int m = idx & 262143;
    int k = m >> 10;
    int j = m & 1023;
    const float* src = (srcid == 0) ? wf : (srcid == 1) ? wb : (srcid == 2) ? whf : whb;
    float v = src[j * EE + k];
    if (srcid < 2) g_wt[srcid][((k >> 1) * H4 + j) * 2 + (k & 1)] = v;   // paired over k
    else           g_wt[srcid][k * H4 + j] = v;                          // plain
}

// ---------------- kernel 2: embedding gather + input projections (f32x2) ----------------
__global__ void __launch_bounds__(256, 1) proj_kernel(const int* __restrict__ word_ids,
                                                      const float* __restrict__ embed,
                                                      const float* __restrict__ b_f,
                                                      const float* __restrict__ b_b) {
    extern __shared__ float psm[];
    float* esf = psm;                 // [32][256]   = 8192 floats
    ull*   wsm = (ull*)(psm + 8192);  // [64 k2][256 j] ull = 32768 floats
    __shared__ int wids[32];

    int dir = blockIdx.z;
    int jt  = blockIdx.y;             // j base jt*256
    int tile = blockIdx.x;
    int s  = tile >> 1;
    int b0 = (tile & 1) * 32;
    int t_src = dir ? (TT - 1 - s) : s;
    int tid = threadIdx.x;
    int jb = jt * 256;

    if (tid < 32) wids[tid] = word_ids[(b0 + tid) * TT + t_src];
    __syncthreads();
    for (int i = tid; i < 2048; i += 256) {
        int r = i >> 6, c = i & 63;
        ((float4*)&esf[r * 256])[c] = ((const float4*)(embed + (size_t)wids[r] * EE))[c];
    }

    int tg = tid >> 6;                // 0..3 -> tokens tg*8..tg*8+7
    int jq = tid & 63;                // -> j cols jb + jq*4 .. +3

    ull acc[8][4];
#pragma unroll
    for (int r = 0; r < 8; r++)
#pragma unroll
        for (int c = 0; c < 4; c++) acc[r][c] = 0ull;

    const float4* __restrict__ gw4 = (const float4*)g_wt[dir];

    for (int kc = 0; kc < 2; kc++) {
        __syncthreads();
        for (int i = tid; i < 8192; i += 256) {
            int k2l = i >> 7;
            int jj4 = i & 127;
            ((float4*)wsm)[i] = gw4[((size_t)((kc * 64 + k2l) * H4 + jb) >> 1) + jj4];
        }
        __syncthreads();

#pragma unroll 4
        for (int k2l = 0; k2l < 64; k2l += 2) {
            int kabs4 = kc * 128 + 2 * k2l;
            ulonglong2 a[8];
#pragma unroll
            for (int r = 0; r < 8; r++)
                a[r] = *(const ulonglong2*)&esf[(tg * 8 + r) * 256 + kabs4];
            const ull* wpA = &wsm[k2l * 256 + jq * 4];
            const ull* wpB = &wsm[(k2l + 1) * 256 + jq * 4];
            ulonglong2 wA01 = *(const ulonglong2*)wpA;
            ulonglong2 wA23 = *(const ulonglong2*)(wpA + 2);
            ulonglong2 wB01 = *(const ulonglong2*)wpB;
            ulonglong2 wB23 = *(const ulonglong2*)(wpB + 2);
#pragma unroll
            for (int r = 0; r < 8; r++) {
                fma2(acc[r][0], a[r].x, wA01.x);
                fma2(acc[r][1], a[r].x, wA01.y);
                fma2(acc[r][2], a[r].x, wA23.x);
                fma2(acc[r][3], a[r].x, wA23.y);
                fma2(acc[r][0], a[r].y, wB01.x);
                fma2(acc[r][1], a[r].y, wB01.y);
                fma2(acc[r][2], a[r].y, wB23.x);
                fma2(acc[r][3], a[r].y, wB23.y);
            }
        }
    }

    const float* bias_p = dir ? b_b : b_f;
    int j0 = jb + jq * 4;
    float4 bias = *(const float4*)&bias_p[j0];
    size_t base = ((size_t)dir * TT + s) * (BB * H4);
#pragma unroll
    for (int r = 0; r < 8; r++) {
        int b = b0 + tg * 8 + r;
        float4 v;
        v.x = hsum2(acc[r][0]) + bias.x;
        v.y = hsum2(acc[r][1]) + bias.y;
        v.z = hsum2(acc[r][2]) + bias.z;
        v.w = hsum2(acc[r][3]) + bias.w;
        *(float4*)&g_xp[base + (size_t)b * H4 + j0] = v;
    }
}

// ---------------- kernel 3: persistent BiLSTM, per-warp producer flags, f32x2 ----------------
// grid (64, 2), 256 threads. CTA (bt, et): 8 batch rows x 32 e-cols (all 4 gates local).
// Fine-grained sync: warp w's k-slice depends ONLY on producer CTA w's h columns.
// Each warp polls one flag, group kh (warps 2kh,2kh+1) stages its slice, named bar(64).
__global__ void __launch_bounds__(256, 1) lstm_kernel() {
    extern __shared__ float sm[];
    ull*   ws2 = (ull*)sm;            // [128 k2][128 col] ull  (131072 B)
    float* hs  = sm + 32768;          // [8][256]               (8192 B)
    float* gxp = sm + 32768 + 2048;   // [4 kh][8 row][128 col] (16384 B)

    int dir = blockIdx.y;
    int cta = blockIdx.x;
    int bt = cta >> 3;
    int et = cta & 7;
    int b_base = bt * 8;
    int grp = dir * 8 + bt;
    int tid = threadIdx.x;
    int wid = tid >> 5;               // warp 0..7 -> polls producer CTA wid

    // GEMM thread mapping
    int jp = tid & 63;                // cols 2jp, 2jp+1  (col = g*32+el)
    int kh = tid >> 6;                // k2 in [kh*32, kh*32+32); group = warps 2kh,2kh+1

    // elementwise mapping
    int bl = tid >> 5;                // 0..7
    int el2 = tid & 31;
    int b_e = b_base + bl;
    int e = et * 32 + el2;

    // staging mapping (group-local): 64 threads stage 128 float4 of slice [kh*64, kh*64+64)
    int tg64 = tid & 63;

    // stage W_hh^T slice as k-pairs: ws2[k2*128 + col] = {w[2k2][C], w[2k2+1][C]}
    const float* __restrict__ whh_t = g_wt[2 + dir];
    float* wsf = sm;
    for (int i = tid; i < 32768; i += 256) {
        int k = i >> 7, col = i & 127;
        float v = whh_t[k * H4 + (col >> 5) * 256 + et * 32 + (col & 31)];
        wsf[((k >> 1) * 128 + col) * 2 + (k & 1)] = v;
    }
    // zero h buffer 0 (each CTA owns 256 contiguous elements); L2-direct
    __stcg(&g_h[dir][0][cta * 256 + tid], 0.0f);

    float c_reg = 0.0f;

    group_bar(grp, 8);   // h(0) + flags(=0 from init/reset) visible group-wide

    for (int s = 0; s < TT; s++) {
        int buf = s & 1;

        // prefetch xp into registers (L1-resident stream; overlaps the flag wait)
        const float* __restrict__ xpp = g_xp + ((size_t)dir * TT + s) * (BB * H4);
        float xq0 = xpp[(size_t)b_e * H4 + 0 * 256 + e];
        float xq1 = xpp[(size_t)b_e * H4 + 1 * 256 + e];
        float xq2 = xpp[(size_t)b_e * H4 + 2 * 256 + e];
        float xq3 = xpp[(size_t)b_e * H4 + 3 * 256 + e];

        if (s > 0) {
            // warp wid waits only on its own producer CTA's flag
            if ((tid & 31) == 0) {
                const int* fp = &g_flag[grp * 256 + wid * 32];
                while (ld_acq(fp) < s) { }
            }
            __syncwarp();
        }

        // group-local staging: slice floats [kh*64, kh*64+64) for all 8 rows
        {
            const float* __restrict__ hb = &g_h[dir][buf][b_base * EE];
#pragma unroll
            for (int q = 0; q < 2; q++) {
                int idx = tg64 * 2 + q;          // 0..127
                int row = idx >> 4;              // 0..7
                int c4 = idx & 15;               // 0..15
                float4 v = __ldcg((const float4*)&hb[row * 256 + kh * 64] + c4);
                *((float4*)&hs[row * 256 + kh * 64] + c4) = v;
            }
        }
        named_bar(1 + kh, 64);   // group kh's slice staged

        // GEMM: this thread's k-slice, 2 cols, all 8 rows; 2 k2 per iter
        ull acc[8][2];
#pragma unroll
        for (int r = 0; r < 8; r++) { acc[r][0] = 0ull; acc[r][1] = 0ull; }

        int k2b = kh * 32;
#pragma unroll 4
        for (int k2i = 0; k2i < 32; k2i += 2) {
            int k2 = k2b + k2i;
            ulonglong2 wA = *(const ulonglong2*)&ws2[k2 * 128 + 2 * jp];
            ulonglong2 wB = *(const ulonglong2*)&ws2[(k2 + 1) * 128 + 2 * jp];
#pragma unroll
            for (int r = 0; r < 8; r++) {
                ulonglong2 a = *(const ulonglong2*)&hs[r * 256 + 2 * k2];
                fma2(acc[r][0], a.x, wA.x);
                fma2(acc[r][1], a.x, wA.y);
                fma2(acc[r][0], a.y, wB.x);
                fma2(acc[r][1], a.y, wB.y);
            }
        }
        // write k-partials to exchange smem
#pragma unroll
        for (int r = 0; r < 8; r++) {
            float2 pv;
            pv.x = hsum2(acc[r][0]);
            pv.y = hsum2(acc[r][1]);
            *(float2*)&gxp[kh * 1024 + r * 128 + 2 * jp] = pv;
        }
        __syncthreads();

        // elementwise update (c in register), reduce 4 k-partials
        float g0 = xq0, g1 = xq1, g2 = xq2, g3 = xq3;
#pragma unroll
        for (int q = 0; q < 4; q++) {
            g0 += gxp[q * 1024 + bl * 128 + 0 * 32 + el2];
            g1 += gxp[q * 1024 + bl * 128 + 1 * 32 + el2];
            g2 += gxp[q * 1024 + bl * 128 + 2 * 32 + el2];
            g3 += gxp[q * 1024 + bl * 128 + 3 * 32 + el2];
        }
        float iv = fsig(g0);
        float fv = fsig(g1);
        float gv = ftanh(g2);
        float ov = fsig(g3);
        c_reg = fv * c_reg + iv * gv;
        float h = ov * ftanh(c_reg);
        __stcg(&g_h[dir][buf ^ 1][b_e * EE + e], h);       // L2-direct publish

        __syncthreads();                                   // all h stores before release
        if (s < TT - 1 && tid == 0) st_rel(&g_flag[grp * 256 + et * 32], s + 1);

        // g_seq store AFTER release: excluded from the release's store-drain
        int t_out = dir ? (TT - 1 - s) : s;
        __stcg(&g_seq[((size_t)b_e * TT + t_out) * 512 + dir * 256 + e], h);
    }

    // terminal barrier, then reset flags for the next graph replay
    group_bar(grp, 8);
    if (tid == 0) g_flag[grp * 256 + et * 32] = 0;
}

// ---------------- kernel 4: LayerNorm + classifier + argmax ----------------
__global__ void ln_logits_kernel(const float* __restrict__ gamma, const float* __restrict__ beta,
                                 const float* __restrict__ cls_w, const float* __restrict__ cls_b,
                                 float* __restrict__ out, int out_size) {
    int tok = blockIdx.x;
    int tid = threadIdx.x;
    int lane = tid & 31;
    int warp = tid >> 5;

    float4 v = ((const float4*)(g_seq + (size_t)tok * 512))[tid];
    float s1 = v.x + v.y + v.z + v.w;
    float s2 = v.x * v.x + v.y * v.y + v.z * v.z + v.w * v.w;
#pragma unroll
    for (int off = 16; off; off >>= 1) {
        s1 += __shfl_down_sync(0xffffffffu, s1, off);
        s2 += __shfl_down_sync(0xffffffffu, s2, off);
    }
    __shared__ float a1[4], a2[4];
    __shared__ float mu_s, rstd_s;
    if (lane == 0) { a1[warp] = s1; a2[warp] = s2; }
    __syncthreads();
    if (tid == 0) {
        float t1 = a1[0] + a1[1] + a1[2] + a1[3];
        float t2 = a2[0] + a2[1] + a2[2] + a2[3];
        float mu = t1 * (1.0f / 512.0f);
        float var = t2 * (1.0f / 512.0f) - mu * mu;
        mu_s = mu;
        rstd_s = rsqrtf(var + 1e-5f);
    }
    __syncthreads();
    float mu = mu_s, rstd = rstd_s;

    float4 gm = ((const float4*)gamma)[tid];
    float4 bt = ((const float4*)beta)[tid];
    float4 y;
    y.x = (v.x - mu) * rstd * gm.x + bt.x;
    y.y = (v.y - mu) * rstd * gm.y + bt.y;
    y.z = (v.z - mu) * rstd * gm.z + bt.z;
    y.w = (v.w - mu) * rstd * gm.w + bt.w;

    float p[KK];
#pragma unroll
    for (int k = 0; k < KK; k++) {
        float4 w = ((const float4*)(cls_w + k * 512))[tid];
        p[k] = y.x * w.x + y.y * w.y + y.z * w.z + y.w * w.w;
    }
#pragma unroll
    for (int off = 16; off; off >>= 1) {
#pragma unroll
        for (int k = 0; k < KK; k++) p[k] += __shfl_down_sync(0xffffffffu, p[k], off);
    }
    __shared__ float wp[4][KK];
    __shared__ float lg[KK];
    if (lane == 0) {
#pragma unroll
        for (int k = 0; k < KK; k++) wp[warp][k] = p[k];
    }
    __syncthreads();
    if (tid < KK) {
        float l = wp[0][tid] + wp[1][tid] + wp[2][tid] + wp[3][tid] + cls_b[tid];
        g_logits[tok * KK + tid] = l;
        lg[tid] = l;
    }
    __syncthreads();
    if (tid == 0) {
        int am = 0;
        float bv = lg[0];
#pragma unroll
        for (int k = 1; k < KK; k++) { if (lg[k] > bv) { bv = lg[k]; am = k; } }
        if (1 + tok < out_size) out[1 + tok] = (float)am;
    }
}

// ---------------- kernel 5: CRF, one warp per batch ----------------
__global__ void crf_kernel(const int* __restrict__ label_ids, const float* __restrict__ crf_start,
                           const float* __restrict__ crf_end, const float* __restrict__ crf_trans) {
    int b = blockIdx.x;
    int lane = threadIdx.x;
    const unsigned FULL = 0xffffffffu;

    float num = 0.0f;
    for (int t = lane; t < TT; t += 32) {
        int tg = label_ids[b * TT + t];
        num += g_logits[(b * TT + t) * KK + tg];
        if (t < TT - 1) num += crf_trans[tg * KK + label_ids[b * TT + t + 1]];
    }
#pragma unroll
    for (int off = 16; off; off >>= 1) num += __shfl_down_sync(FULL, num, off);
    if (lane == 0) {
        num += crf_start[label_ids[b * TT]] + crf_end[label_ids[b * TT + TT - 1]];
    }

    bool act = lane < KK;
    float tcol[KK];
#pragma unroll
    for (int k = 0; k < KK; k++) tcol[k] = act ? crf_trans[k * KK + lane] : 0.0f;
    float alpha = act ? (crf_start[lane] + g_logits[(size_t)b * TT * KK + lane]) : -1e30f;

    for (int t = 1; t < TT; t++) {
        float em = act ? g_logits[((size_t)b * TT + t) * KK + lane] : 0.0f;
        float va[KK];
#pragma unroll
        for (int k = 0; k < KK; k++) va[k] = __shfl_sync(FULL, alpha, k) + tcol[k];
        float m = va[0];
#pragma unroll
        for (int k = 1; k < KK; k++) m = fmaxf(m, va[k]);
        float sme = 0.0f;
#pragma unroll
        for (int k = 0; k < KK; k++) sme += expf(va[k] - m);
        float na = em + m + logf(sme);
        alpha = act ? na : -1e30f;
    }

    float v = act ? (alpha + crf_end[lane]) : -1e30f;
    float m = v;
#pragma unroll
    for (int off = 16; off; off >>= 1) m = fmaxf(m, __shfl_xor_sync(FULL, m, off));
    float e = expf(v - m);
#pragma unroll
    for (int off = 16; off; off >>= 1) e += __shfl_xor_sync(FULL, e, off);
    float logZ = m + logf(e);

    if (lane == 0) g_llh[b] = num - logZ;
}

// ---------------- kernel 6: final loss reduction ----------------
__global__ void loss_kernel(float* __restrict__ out) {
    __shared__ float s[BB];
    int tid = threadIdx.x;
    s[tid] = g_llh[tid];
    __syncthreads();
    for (int off = 32; off; off >>= 1) {
        if (tid < off) s[tid] += s[tid + off];
        __syncthreads();
    }
    if (tid == 0) out[0] = -s[0];
}

// ---------------- launch ----------------
extern "C" void kernel_launch(void* const* d_in, const int* in_sizes, int n_in,
                              void* d_out, int out_size) {
    const int*   word_ids  = (const int*)d_in[0];
    const int*   label_ids = (const int*)d_in[1];
    const float* embed     = (const float*)d_in[2];
    const float* w_ih_f    = (const float*)d_in[3];
    const float* w_hh_f    = (const float*)d_in[4];
    const float* b_f       = (const float*)d_in[5];
    const float* w_ih_b    = (const float*)d_in[6];
    const float* w_hh_b    = (const float*)d_in[7];
    const float* b_b       = (const float*)d_in[8];
    const float* ln_gamma  = (const float*)d_in[9];
    const float* ln_beta   = (const float*)d_in[10];
    const float* cls_w     = (const float*)d_in[11];
    const float* cls_b     = (const float*)d_in[12];
    const float* crf_start = (const float*)d_in[13];
    const float* crf_end   = (const float*)d_in[14];
    const float* crf_trans = (const float*)d_in[15];
    float* out = (float*)d_out;

    const int PROJ_SMEM = (8192 + 32768) * 4;           // 163840 B
    const int LSTM_SMEM = (32768 + 2048 + 4096) * 4;    // 155648 B
    cudaFuncSetAttribute(proj_kernel, cudaFuncAttributeMaxDynamicSharedMemorySize, PROJ_SMEM);
    cudaFuncSetAttribute(lstm_kernel, cudaFuncAttributeMaxDynamicSharedMemorySize, LSTM_SMEM);

    transpose_w_kernel<<<4096, 256>>>(w_ih_f, w_ih_b, w_hh_f, w_hh_b);
    proj_kernel<<<dim3(1024, 4, 2), 256, PROJ_SMEM>>>(word_ids, embed, b_f, b_b);
    lstm_kernel<<<dim3(64, 2), 256, LSTM_SMEM>>>();
    ln_logits_kernel<<<32768, 128>>>(ln_gamma, ln_beta, cls_w, cls_b, out, out_size);
    crf_kernel<<<BB, 32>>>(label_ids, crf_start, crf_end, crf_trans);
    loss_kernel<<<1, BB>>>(out);
}

// round 14
// speedup vs baseline: 1.8513x; 1.0449x over previous
#include <cuda_runtime.h>
#include <cstdint>

#define BB 64
#define TT 512
#define EE 256
#define H4 1024
#define KK 9

typedef unsigned long long ull;

// ---------------- device scratch (static) ----------------
// ih weights (idx 0,1): paired layout  float[((k>>1)*H4 + j)*2 + (k&1)]  == ull[k2*H4 + j]
// hh weights (idx 2,3): plain          float[k*H4 + j]
__device__ float g_wt[4][EE * H4];
__device__ float g_xp[2 * TT * BB * H4];       // [dir][step][b][j]
__device__ float g_seq[(size_t)BB * TT * 512]; // [b][t][2H]
__device__ float g_h[2][2][BB * EE];           // [dir][parity][b*E+e]
__device__ float g_logits[BB * TT * KK];
__device__ float g_llh[BB];
// per-(dir,bt)-group step flags: flag[grp*256 + et*32] = steps published (monotone in-run)
__device__ int g_flag[16 * 256];
// init/terminal barrier (gen snapshot-compared -> replay-safe)
__device__ int g_bar_count[16 * 32];
__device__ int g_bar_gen[16 * 32];

__device__ __forceinline__ float fsig(float x) {
    return __fdividef(1.0f, 1.0f + __expf(-x));
}
__device__ __forceinline__ float ftanh(float x) {
    return __fdividef(2.0f, 1.0f + __expf(-2.0f * x)) - 1.0f;
}

__device__ __forceinline__ void fma2(ull& d, ull a, ull b) {
    asm("fma.rn.f32x2 %0, %1, %2, %0;" : "+l"(d) : "l"(a), "l"(b));
}
__device__ __forceinline__ float hsum2(ull v) {
    float lo, hi;
    asm("mov.b64 {%0,%1}, %2;" : "=f"(lo), "=f"(hi) : "l"(v));
    return lo + hi;
}

// strong-GPU flag ops: no fence instruction, no CCTL.IVALL (L1 untouched)
__device__ __forceinline__ int ld_acq(const int* p) {
    int v;
    asm volatile("ld.acquire.gpu.global.b32 %0, [%1];" : "=r"(v) : "l"(p) : "memory");
    return v;
}
__device__ __forceinline__ void st_rel(int* p, int v) {
    asm volatile("st.release.gpu.global.b32 [%0], %1;" :: "l"(p), "r"(v) : "memory");
}
__device__ __forceinline__ void named_bar(int id, int cnt) {
    asm volatile("bar.sync %0, %1;" :: "r"(id), "r"(cnt) : "memory");
}

// ---------------- group barrier (init/terminal use only) ----------------
__device__ __forceinline__ void group_bar(int id, int n) {
    __syncthreads();
    if (threadIdx.x == 0) {
        int* cnt = &g_bar_count[id * 32];
        int* gen = &g_bar_gen[id * 32];
        int g0 = *(volatile int*)gen;
        __threadfence();
        int t = atomicAdd(cnt, 1);
        if (t == n - 1) {
            *cnt = 0;
            __threadfence();
            atomicAdd(gen, 1);
        } else {
            while (*(volatile int*)gen == g0) { __nanosleep(32); }
            __threadfence();
        }
    }
    __syncthreads();
}

// ---------------- kernel 1: weight transpose/pack ----------------
__global__ void transpose_w_kernel(const float* __restrict__ wf, const float* __restrict__ wb,
                                   const float* __restrict__ whf, const float* __restrict__ whb) {
    int idx = blockIdx.x * 256 + threadIdx.x;      // 4 * 262144 total
    int srcid = idx >> 18;
    int m = idx & 262143;
    int k = m >> 10;
    int j = m & 1023;
    const float* src = (srcid == 0) ? wf : (srcid == 1) ? wb : (srcid == 2) ? whf : whb;
    float v = src[j * EE + k];
    if (srcid < 2) g_wt[srcid][((k >> 1) * H4 + j) * 2 + (k & 1)] = v;   // paired over k
    else           g_wt[srcid][k * H4 + j] = v;                          // plain
}

// ---------------- kernel 2: embedding gather + input projections (f32x2) ----------------
__global__ void __launch_bounds__(256, 1) proj_kernel(const int* __restrict__ word_ids,
                                                      const float* __restrict__ embed,
                                                      const float* __restrict__ b_f,
                                                      const float* __restrict__ b_b) {
    extern __shared__ float psm[];
    float* esf = psm;                 // [32][256]   = 8192 floats
    ull*   wsm = (ull*)(psm + 8192);  // [64 k2][256 j] ull = 32768 floats
    __shared__ int wids[32];

    int dir = blockIdx.z;
    int jt  = blockIdx.y;             // j base jt*256
    int tile = blockIdx.x;
    int s  = tile >> 1;
    int b0 = (tile & 1) * 32;
    int t_src = dir ? (TT - 1 - s) : s;
    int tid = threadIdx.x;
    int jb = jt * 256;

    if (tid < 32) wids[tid] = word_ids[(b0 + tid) * TT + t_src];
    __syncthreads();
    for (int i = tid; i < 2048; i += 256) {
        int r = i >> 6, c = i & 63;
        ((float4*)&esf[r * 256])[c] = ((const float4*)(embed + (size_t)wids[r] * EE))[c];
    }

    int tg = tid >> 6;                // 0..3 -> tokens tg*8..tg*8+7
    int jq = tid & 63;                // -> j cols jb + jq*4 .. +3

    ull acc[8][4];
#pragma unroll
    for (int r = 0; r < 8; r++)
#pragma unroll
        for (int c = 0; c < 4; c++) acc[r][c] = 0ull;

    const float4* __restrict__ gw4 = (const float4*)g_wt[dir];

    for (int kc = 0; kc < 2; kc++) {
        __syncthreads();
        for (int i = tid; i < 8192; i += 256) {
            int k2l = i >> 7;
            int jj4 = i & 127;
            ((float4*)wsm)[i] = gw4[((size_t)((kc * 64 + k2l) * H4 + jb) >> 1) + jj4];
        }
        __syncthreads();

#pragma unroll 4
        for (int k2l = 0; k2l < 64; k2l += 2) {
            int kabs4 = kc * 128 + 2 * k2l;
            ulonglong2 a[8];
#pragma unroll
            for (int r = 0; r < 8; r++)
                a[r] = *(const ulonglong2*)&esf[(tg * 8 + r) * 256 + kabs4];
            const ull* wpA = &wsm[k2l * 256 + jq * 4];
            const ull* wpB = &wsm[(k2l + 1) * 256 + jq * 4];
            ulonglong2 wA01 = *(const ulonglong2*)wpA;
            ulonglong2 wA23 = *(const ulonglong2*)(wpA + 2);
            ulonglong2 wB01 = *(const ulonglong2*)wpB;
            ulonglong2 wB23 = *(const ulonglong2*)(wpB + 2);
#pragma unroll
            for (int r = 0; r < 8; r++) {
                fma2(acc[r][0], a[r].x, wA01.x);
                fma2(acc[r][1], a[r].x, wA01.y);
                fma2(acc[r][2], a[r].x, wA23.x);
                fma2(acc[r][3], a[r].x, wA23.y);
                fma2(acc[r][0], a[r].y, wB01.x);
                fma2(acc[r][1], a[r].y, wB01.y);
                fma2(acc[r][2], a[r].y, wB23.x);
                fma2(acc[r][3], a[r].y, wB23.y);
            }
        }
    }

    const float* bias_p = dir ? b_b : b_f;
    int j0 = jb + jq * 4;
    float4 bias = *(const float4*)&bias_p[j0];
    size_t base = ((size_t)dir * TT + s) * (BB * H4);
#pragma unroll
    for (int r = 0; r < 8; r++) {
        int b = b0 + tg * 8 + r;
        float4 v;
        v.x = hsum2(acc[r][0]) + bias.x;
        v.y = hsum2(acc[r][1]) + bias.y;
        v.z = hsum2(acc[r][2]) + bias.z;
        v.w = hsum2(acc[r][3]) + bias.w;
        *(float4*)&g_xp[base + (size_t)b * H4 + j0] = v;
    }
}

// ---------------- kernel 3: persistent BiLSTM, 512 threads (4 warps/SMSP), f32x2 ----------------
// grid (64, 2), 512 threads. CTA (bt, et): 8 batch rows x 32 e-cols (all 4 gates local).
// k split 8 ways (kh = tid>>6, 16 k2 each). Group kh = warps {2kh, 2kh+1} depends only on
// producer CTA kh: each warp polls one flag, group stages its 1KB slice, named bar(64).
__global__ void __launch_bounds__(512, 1) lstm_kernel() {
    extern __shared__ float sm[];
    ull*   ws2 = (ull*)sm;            // [128 k2][128 col] ull  (131072 B)
    float* hs  = sm + 32768;          // [8][256]               (8192 B)
    float* gxp = sm + 32768 + 2048;   // [8 kh][8 row][128 col] (32768 B)

    int dir = blockIdx.y;
    int cta = blockIdx.x;
    int bt = cta >> 3;
    int et = cta & 7;
    int b_base = bt * 8;
    int grp = dir * 8 + bt;
    int tid = threadIdx.x;

    // GEMM thread mapping
    int jp = tid & 63;                // cols 2jp, 2jp+1  (col = g*32+el)
    int kh = tid >> 6;                // 0..7: k2 in [kh*16, kh*16+16); group = warps 2kh,2kh+1
    int tg64 = tid & 63;              // staging lane within group

    // elementwise mapping (threads 0..255)
    int bl = tid >> 5;                // 0..7 (valid when tid<256)
    int el2 = tid & 31;
    int b_e = b_base + (bl & 7);
    int e = et * 32 + el2;

    // stage W_hh^T slice as k-pairs: ws2[k2*128 + col] = {w[2k2][C], w[2k2+1][C]}
    const float* __restrict__ whh_t = g_wt[2 + dir];
    float* wsf = sm;
    for (int i = tid; i < 32768; i += 512) {
        int k = i >> 7, col = i & 127;
        float v = whh_t[k * H4 + (col >> 5) * 256 + et * 32 + (col & 31)];
        wsf[((k >> 1) * 128 + col) * 2 + (k & 1)] = v;
    }
    // zero h buffer 0 (each CTA owns 256 contiguous elements); L2-direct
    if (tid < 256) __stcg(&g_h[dir][0][cta * 256 + tid], 0.0f);

    float c_reg = 0.0f;

    group_bar(grp, 8);   // h(0) + flags(=0 from init/reset) visible group-wide

    for (int s = 0; s < TT; s++) {
        int buf = s & 1;

        // prefetch xp into registers (L1-resident stream; overlaps the flag wait)
        float xq0 = 0.f, xq1 = 0.f, xq2 = 0.f, xq3 = 0.f;
        if (tid < 256) {
            const float* __restrict__ xpp = g_xp + ((size_t)dir * TT + s) * (BB * H4);
            xq0 = xpp[(size_t)b_e * H4 + 0 * 256 + e];
            xq1 = xpp[(size_t)b_e * H4 + 1 * 256 + e];
            xq2 = xpp[(size_t)b_e * H4 + 2 * 256 + e];
            xq3 = xpp[(size_t)b_e * H4 + 3 * 256 + e];
        }

        if (s > 0) {
            // each warp waits only on its producer CTA (= kh) flag
            if ((tid & 31) == 0) {
                const int* fp = &g_flag[grp * 256 + kh * 32];
                while (ld_acq(fp) < s) { }
            }
            __syncwarp();
        }

        // group-local staging: slice floats [kh*32, kh*32+32) for all 8 rows (64 x float4)
        {
            const float* __restrict__ hb = &g_h[dir][buf][b_base * EE];
            int row = tg64 >> 3;             // 0..7
            int c4  = tg64 & 7;              // 0..7
            float4 v = __ldcg((const float4*)&hb[row * 256 + kh * 32] + c4);
            *((float4*)&hs[row * 256 + kh * 32] + c4) = v;
        }
        named_bar(1 + kh, 64);   // group kh's slice staged

        // GEMM: this thread's k-slice (16 k2), 2 cols, all 8 rows; 2 k2 per iter
        ull acc[8][2];
#pragma unroll
        for (int r = 0; r < 8; r++) { acc[r][0] = 0ull; acc[r][1] = 0ull; }

        int k2b = kh * 16;
#pragma unroll
        for (int k2i = 0; k2i < 16; k2i += 2) {
            int k2 = k2b + k2i;
            ulonglong2 wA = *(const ulonglong2*)&ws2[k2 * 128 + 2 * jp];
            ulonglong2 wB = *(const ulonglong2*)&ws2[(k2 + 1) * 128 + 2 * jp];
#pragma unroll
            for (int r = 0; r < 8; r++) {
                ulonglong2 a = *(const ulonglong2*)&hs[r * 256 + 2 * k2];
                fma2(acc[r][0], a.x, wA.x);
                fma2(acc[r][1], a.x, wA.y);
                fma2(acc[r][0], a.y, wB.x);
                fma2(acc[r][1], a.y, wB.y);
            }
        }
        // write k-partials to exchange smem
#pragma unroll
        for (int r = 0; r < 8; r++) {
            float2 pv;
            pv.x = hsum2(acc[r][0]);
            pv.y = hsum2(acc[r][1]);
            *(float2*)&gxp[kh * 1024 + r * 128 + 2 * jp] = pv;
        }
        __syncthreads();

        float h = 0.0f;
        if (tid < 256) {
            // elementwise update (c in register), reduce 8 k-partials
            float g0 = xq0, g1 = xq1, g2 = xq2, g3 = xq3;
#pragma unroll
            for (int q = 0; q < 8; q++) {
                g0 += gxp[q * 1024 + bl * 128 + 0 * 32 + el2];
                g1 += gxp[q * 1024 + bl * 128 + 1 * 32 + el2];
                g2 += gxp[q * 1024 + bl * 128 + 2 * 32 + el2];
                g3 += gxp[q * 1024 + bl * 128 + 3 * 32 + el2];
            }
            float iv = fsig(g0);
            float fv = fsig(g1);
            float gv = ftanh(g2);
            float ov = fsig(g3);
            c_reg = fv * c_reg + iv * gv;
            h = ov * ftanh(c_reg);
            __stcg(&g_h[dir][buf ^ 1][b_e * EE + e], h);   // L2-direct publish
        }

        __syncthreads();                                   // all h stores before release
        if (s < TT - 1 && tid == 0) st_rel(&g_flag[grp * 256 + et * 32], s + 1);

        // g_seq store AFTER release: excluded from the release's store-drain
        if (tid < 256) {
            int t_out = dir ? (TT - 1 - s) : s;
            __stcg(&g_seq[((size_t)b_e * TT + t_out) * 512 + dir * 256 + e], h);
        }
    }

    // terminal barrier, then reset flags for the next graph replay
    group_bar(grp, 8);
    if (tid == 0) g_flag[grp * 256 + et * 32] = 0;
}

// ---------------- kernel 4: LayerNorm + classifier + argmax ----------------
__global__ void ln_logits_kernel(const float* __restrict__ gamma, const float* __restrict__ beta,
                                 const float* __restrict__ cls_w, const float* __restrict__ cls_b,
                                 float* __restrict__ out, int out_size) {
    int tok = blockIdx.x;
    int tid = threadIdx.x;
    int lane = tid & 31;
    int warp = tid >> 5;

    float4 v = ((const float4*)(g_seq + (size_t)tok * 512))[tid];
    float s1 = v.x + v.y + v.z + v.w;
    float s2 = v.x * v.x + v.y * v.y + v.z * v.z + v.w * v.w;
#pragma unroll
    for (int off = 16; off; off >>= 1) {
        s1 += __shfl_down_sync(0xffffffffu, s1, off);
        s2 += __shfl_down_sync(0xffffffffu, s2, off);
    }
    __shared__ float a1[4], a2[4];
    __shared__ float mu_s, rstd_s;
    if (lane == 0) { a1[warp] = s1; a2[warp] = s2; }
    __syncthreads();
    if (tid == 0) {
        float t1 = a1[0] + a1[1] + a1[2] + a1[3];
        float t2 = a2[0] + a2[1] + a2[2] + a2[3];
        float mu = t1 * (1.0f / 512.0f);
        float var = t2 * (1.0f / 512.0f) - mu * mu;
        mu_s = mu;
        rstd_s = rsqrtf(var + 1e-5f);
    }
    __syncthreads();
    float mu = mu_s, rstd = rstd_s;

    float4 gm = ((const float4*)gamma)[tid];
    float4 bt = ((const float4*)beta)[tid];
    float4 y;
    y.x = (v.x - mu) * rstd * gm.x + bt.x;
    y.y = (v.y - mu) * rstd * gm.y + bt.y;
    y.z = (v.z - mu) * rstd * gm.z + bt.z;
    y.w = (v.w - mu) * rstd * gm.w + bt.w;

    float p[KK];
#pragma unroll
    for (int k = 0; k < KK; k++) {
        float4 w = ((const float4*)(cls_w + k * 512))[tid];
        p[k] = y.x * w.x + y.y * w.y + y.z * w.z + y.w * w.w;
    }
#pragma unroll
    for (int off = 16; off; off >>= 1) {
#pragma unroll
        for (int k = 0; k < KK; k++) p[k] += __shfl_down_sync(0xffffffffu, p[k], off);
    }
    __shared__ float wp[4][KK];
    __shared__ float lg[KK];
    if (lane == 0) {
#pragma unroll
        for (int k = 0; k < KK; k++) wp[warp][k] = p[k];
    }
    __syncthreads();
    if (tid < KK) {
        float l = wp[0][tid] + wp[1][tid] + wp[2][tid] + wp[3][tid] + cls_b[tid];
        g_logits[tok * KK + tid] = l;
        lg[tid] = l;
    }
    __syncthreads();
    if (tid == 0) {
        int am = 0;
        float bv = lg[0];
#pragma unroll
        for (int k = 1; k < KK; k++) { if (lg[k] > bv) { bv = lg[k]; am = k; } }
        if (1 + tok < out_size) out[1 + tok] = (float)am;
    }
}

// ---------------- kernel 5: CRF, one warp per batch ----------------
__global__ void crf_kernel(const int* __restrict__ label_ids, const float* __restrict__ crf_start,
                           const float* __restrict__ crf_end, const float* __restrict__ crf_trans) {
    int b = blockIdx.x;
    int lane = threadIdx.x;
    const unsigned FULL = 0xffffffffu;

    float num = 0.0f;
    for (int t = lane; t < TT; t += 32) {
        int tg = label_ids[b * TT + t];
        num += g_logits[(b * TT + t) * KK + tg];
        if (t < TT - 1) num += crf_trans[tg * KK + label_ids[b * TT + t + 1]];
    }
#pragma unroll
    for (int off = 16; off; off >>= 1) num += __shfl_down_sync(FULL, num, off);
    if (lane == 0) {
        num += crf_start[label_ids[b * TT]] + crf_end[label_ids[b * TT + TT - 1]];
    }

    bool act = lane < KK;
    float tcol[KK];
#pragma unroll
    for (int k = 0; k < KK; k++) tcol[k] = act ? crf_trans[k * KK + lane] : 0.0f;
    float alpha = act ? (crf_start[lane] + g_logits[(size_t)b * TT * KK + lane]) : -1e30f;

    for (int t = 1; t < TT; t++) {
        float em = act ? g_logits[((size_t)b * TT + t) * KK + lane] : 0.0f;
        float va[KK];
#pragma unroll
        for (int k = 0; k < KK; k++) va[k] = __shfl_sync(FULL, alpha, k) + tcol[k];
        float m = va[0];
#pragma unroll
        for (int k = 1; k < KK; k++) m = fmaxf(m, va[k]);
        float sme = 0.0f;
#pragma unroll
        for (int k = 0; k < KK; k++) sme += expf(va[k] - m);
        float na = em + m + logf(sme);
        alpha = act ? na : -1e30f;
    }

    float v = act ? (alpha + crf_end[lane]) : -1e30f;
    float m = v;
#pragma unroll
    for (int off = 16; off; off >>= 1) m = fmaxf(m, __shfl_xor_sync(FULL, m, off));
    float e = expf(v - m);
#pragma unroll
    for (int off = 16; off; off >>= 1) e += __shfl_xor_sync(FULL, e, off);
    float logZ = m + logf(e);

    if (lane == 0) g_llh[b] = num - logZ;
}

// ---------------- kernel 6: final loss reduction ----------------
__global__ void loss_kernel(float* __restrict__ out) {
    __shared__ float s[BB];
    int tid = threadIdx.x;
    s[tid] = g_llh[tid];
    __syncthreads();
    for (int off = 32; off; off >>= 1) {
        if (tid < off) s[tid] += s[tid + off];
        __syncthreads();
    }
    if (tid == 0) out[0] = -s[0];
}

// ---------------- launch ----------------
extern "C" void kernel_launch(void* const* d_in, const int* in_sizes, int n_in,
                              void* d_out, int out_size) {
    const int*   word_ids  = (const int*)d_in[0];
    const int*   label_ids = (const int*)d_in[1];
    const float* embed     = (const float*)d_in[2];
    const float* w_ih_f    = (const float*)d_in[3];
    const float* w_hh_f    = (const float*)d_in[4];
    const float* b_f       = (const float*)d_in[5];
    const float* w_ih_b    = (const float*)d_in[6];
    const float* w_hh_b    = (const float*)d_in[7];
    const float* b_b       = (const float*)d_in[8];
    const float* ln_gamma  = (const float*)d_in[9];
    const float* ln_beta   = (const float*)d_in[10];
    const float* cls_w     = (const float*)d_in[11];
    const float* cls_b     = (const float*)d_in[12];
    const float* crf_start = (const float*)d_in[13];
    const float* crf_end   = (const float*)d_in[14];
    const float* crf_trans = (const float*)d_in[15];
    float* out = (float*)d_out;

    const int PROJ_SMEM = (8192 + 32768) * 4;           // 163840 B
    const int LSTM_SMEM = (32768 + 2048 + 8192) * 4;    // 172032 B
    cudaFuncSetAttribute(proj_kernel, cudaFuncAttributeMaxDynamicSharedMemorySize, PROJ_SMEM);
    cudaFuncSetAttribute(lstm_kernel, cudaFuncAttributeMaxDynamicSharedMemorySize, LSTM_SMEM);

    transpose_w_kernel<<<4096, 256>>>(w_ih_f, w_ih_b, w_hh_f, w_hh_b);
    proj_kernel<<<dim3(1024, 4, 2), 256, PROJ_SMEM>>>(word_ids, embed, b_f, b_b);
    lstm_kernel<<<dim3(64, 2), 512, LSTM_SMEM>>>();
    ln_logits_kernel<<<32768, 128>>>(ln_gamma, ln_beta, cls_w, cls_b, out, out_size);
    crf_kernel<<<BB, 32>>>(label_ids, crf_start, crf_end, crf_trans);
    loss_kernel<<<1, BB>>>(out);
}

// round 16
// speedup vs baseline: 2.0200x; 1.0911x over previous
#include <cuda_runtime.h>
#include <cstdint>

#define BB 64
#define TT 512
#define EE 256
#define H4 1024
#define KK 9

typedef unsigned long long ull;

// ---------------- device scratch (static) ----------------
// ih weights (idx 0,1): paired layout  float[((k>>1)*H4 + j)*2 + (k&1)]  == ull[k2*H4 + j]
// hh weights (idx 2,3): plain          float[k*H4 + j]
__device__ float g_wt[4][EE * H4];
__device__ float g_xp[2 * TT * BB * H4];       // [dir][step][b][j]
__device__ float g_seq[(size_t)BB * TT * 512]; // [b][t][2H]
__device__ float g_h[2][2][BB * EE];           // [dir][parity][b*E+e]
__device__ float g_logits[BB * TT * KK];
__device__ float g_llh[BB];
// per-(dir,bt)-group step flags: flag[grp*256 + et*32] = steps published (monotone in-run)
__device__ int g_flag[16 * 256];
// init/terminal barrier (gen snapshot-compared -> replay-safe)
__device__ int g_bar_count[16 * 32];
__device__ int g_bar_gen[16 * 32];

__device__ __forceinline__ float fsig(float x) {
    return __fdividef(1.0f, 1.0f + __expf(-x));
}
__device__ __forceinline__ float ftanh(float x) {
    return __fdividef(2.0f, 1.0f + __expf(-2.0f * x)) - 1.0f;
}

__device__ __forceinline__ void fma2(ull& d, ull a, ull b) {
    asm("fma.rn.f32x2 %0, %1, %2, %0;" : "+l"(d) : "l"(a), "l"(b));
}
__device__ __forceinline__ float hsum2(ull v) {
    float lo, hi;
    asm("mov.b64 {%0,%1}, %2;" : "=f"(lo), "=f"(hi) : "l"(v));
    return lo + hi;
}

// strong-GPU flag ops: no fence instruction, no CCTL.IVALL (L1 untouched)
__device__ __forceinline__ int ld_acq(const int* p) {
    int v;
    asm volatile("ld.acquire.gpu.global.b32 %0, [%1];" : "=r"(v) : "l"(p) : "memory");
    return v;
}
__device__ __forceinline__ void st_rel(int* p, int v) {
    asm volatile("st.release.gpu.global.b32 [%0], %1;" :: "l"(p), "r"(v) : "memory");
}
__device__ __forceinline__ void named_bar(int id, int cnt) {
    asm volatile("bar.sync %0, %1;" :: "r"(id), "r"(cnt) : "memory");
}

// ---------------- group barrier (init/terminal use only) ----------------
__device__ __forceinline__ void group_bar(int id, int n) {
    __syncthreads();
    if (threadIdx.x == 0) {
        int* cnt = &g_bar_count[id * 32];
        int* gen = &g_bar_gen[id * 32];
        int g0 = *(volatile int*)gen;
        __threadfence();
        int t = atomicAdd(cnt, 1);
        if (t == n - 1) {
            *cnt = 0;
            __threadfence();
            atomicAdd(gen, 1);
        } else {
            while (*(volatile int*)gen == g0) { __nanosleep(32); }
            __threadfence();
        }
    }
    __syncthreads();
}

// ---------------- kernel 1: weight transpose/pack ----------------
__global__ void transpose_w_kernel(const float* __restrict__ wf, const float* __restrict__ wb,
                                   const float* __restrict__ whf, const float* __restrict__ whb) {
    int idx = blockIdx.x * 256 + threadIdx.x;      // 4 * 262144 total
    int srcid = idx >> 18;
    int m = idx & 262143;
    int k = m >> 10;
    int j = m & 1023;
    const float* src = (srcid == 0) ? wf : (srcid == 1) ? wb : (srcid == 2) ? whf : whb;
    float v = src[j * EE + k];
    if (srcid < 2) g_wt[srcid][((k >> 1) * H4 + j) * 2 + (k & 1)] = v;   // paired over k
    else           g_wt[srcid][k * H4 + j] = v;                          // plain
}

// ---------------- kernel 2: embedding gather + input projections (f32x2) ----------------
// grid (512 s-tiles, 4 j-tiles of 256, 2 dirs), 512 threads.
// CTA: 64 tokens (one full s) x 256 j; weights staged through smem in 2 k-chunks,
// each chunk now amortized over 64 tokens (2x reuse vs R14) with 4 warps/SMSP.
__global__ void __launch_bounds__(512, 1) proj_kernel(const int* __restrict__ word_ids,
                                                      const float* __restrict__ embed,
                                                      const float* __restrict__ b_f,
                                                      const float* __restrict__ b_b) {
    extern __shared__ float psm[];
    float* esf = psm;                  // [64][256]   = 16384 floats
    ull*   wsm = (ull*)(psm + 16384);  // [64 k2][256 j] ull = 32768 floats
    __shared__ int wids[64];

    int dir = blockIdx.z;
    int jt  = blockIdx.y;             // j base jt*256
    int s   = blockIdx.x;             // one timestep, all 64 batch rows
    int t_src = dir ? (TT - 1 - s) : s;
    int tid = threadIdx.x;
    int jb = jt * 256;

    if (tid < 64) wids[tid] = word_ids[tid * TT + t_src];
    __syncthreads();
    // stage 64 embedding rows (4096 float4)
    for (int i = tid; i < 4096; i += 512) {
        int r = i >> 6, c = i & 63;
        ((float4*)&esf[r * 256])[c] = ((const float4*)(embed + (size_t)wids[r] * EE))[c];
    }

    int tg = tid >> 6;                // 0..7 -> tokens tg*8..tg*8+7
    int jq = tid & 63;                // -> j cols jb + jq*4 .. +3

    ull acc[8][4];
#pragma unroll
    for (int r = 0; r < 8; r++)
#pragma unroll
        for (int c = 0; c < 4; c++) acc[r][c] = 0ull;

    const float4* __restrict__ gw4 = (const float4*)g_wt[dir];

    for (int kc = 0; kc < 2; kc++) {
        __syncthreads();
        // stage weight chunk: k2 in [kc*64, kc*64+64), j in [jb, jb+256)
        for (int i = tid; i < 8192; i += 512) {
            int k2l = i >> 7;
            int jj4 = i & 127;
            ((float4*)wsm)[i] = gw4[((size_t)((kc * 64 + k2l) * H4 + jb) >> 1) + jj4];
        }
        __syncthreads();

        // 2 k2 per iteration: a loaded as one 16B broadcast (covers k2, k2+1)
#pragma unroll 4
        for (int k2l = 0; k2l < 64; k2l += 2) {
            int kabs4 = kc * 128 + 2 * k2l;
            ulonglong2 a[8];
#pragma unroll
            for (int r = 0; r < 8; r++)
                a[r] = *(const ulonglong2*)&esf[(tg * 8 + r) * 256 + kabs4];
            const ull* wpA = &wsm[k2l * 256 + jq * 4];
            const ull* wpB = &wsm[(k2l + 1) * 256 + jq * 4];
            ulonglong2 wA01 = *(const ulonglong2*)wpA;
            ulonglong2 wA23 = *(const ulonglong2*)(wpA + 2);
            ulonglong2 wB01 = *(const ulonglong2*)wpB;
            ulonglong2 wB23 = *(const ulonglong2*)(wpB + 2);
#pragma unroll
            for (int r = 0; r < 8; r++) {
                fma2(acc[r][0], a[r].x, wA01.x);
                fma2(acc[r][1], a[r].x, wA01.y);
                fma2(acc[r][2], a[r].x, wA23.x);
                fma2(acc[r][3], a[r].x, wA23.y);
                fma2(acc[r][0], a[r].y, wB01.x);
                fma2(acc[r][1], a[r].y, wB01.y);
                fma2(acc[r][2], a[r].y, wB23.x);
                fma2(acc[r][3], a[r].y, wB23.y);
            }
        }
    }

    const float* bias_p = dir ? b_b : b_f;
    int j0 = jb + jq * 4;
    float4 bias = *(const float4*)&bias_p[j0];
    size_t base = ((size_t)dir * TT + s) * (BB * H4);
#pragma unroll
    for (int r = 0; r < 8; r++) {
        int b = tg * 8 + r;
        float4 v;
        v.x = hsum2(acc[r][0]) + bias.x;
        v.y = hsum2(acc[r][1]) + bias.y;
        v.z = hsum2(acc[r][2]) + bias.z;
        v.w = hsum2(acc[r][3]) + bias.w;
        *(float4*)&g_xp[base + (size_t)b * H4 + j0] = v;
    }
}

// ---------------- kernel 3: persistent BiLSTM, 512 threads (4 warps/SMSP), f32x2 ----------------
// grid (64, 2), 512 threads. CTA (bt, et): 8 batch rows x 32 e-cols (all 4 gates local).
// k split 8 ways (kh = tid>>6, 16 k2 each). Group kh = warps {2kh, 2kh+1} depends only on
// producer CTA kh: each warp polls one flag, group stages its 1KB slice, named bar(64).
// Release path synchronizes only the 256 elementwise threads (named bar 15).
__global__ void __launch_bounds__(512, 1) lstm_kernel() {
    extern __shared__ float sm[];
    ull*   ws2 = (ull*)sm;            // [128 k2][128 col] ull  (131072 B)
    float* hs  = sm + 32768;          // [8][256]               (8192 B)
    float* gxp = sm + 32768 + 2048;   // [8 kh][8 row][128 col] (32768 B)

    int dir = blockIdx.y;
    int cta = blockIdx.x;
    int bt = cta >> 3;
    int et = cta & 7;
    int b_base = bt * 8;
    int grp = dir * 8 + bt;
    int tid = threadIdx.x;

    // GEMM thread mapping
    int jp = tid & 63;                // cols 2jp, 2jp+1  (col = g*32+el)
    int kh = tid >> 6;                // 0..7: k2 in [kh*16, kh*16+16); group = warps 2kh,2kh+1
    int tg64 = tid & 63;              // staging lane within group

    // elementwise mapping (threads 0..255)
    int bl = tid >> 5;                // 0..7 (valid when tid<256)
    int el2 = tid & 31;
    int b_e = b_base + (bl & 7);
    int e = et * 32 + el2;

    // stage W_hh^T slice as k-pairs: ws2[k2*128 + col] = {w[2k2][C], w[2k2+1][C]}
    const float* __restrict__ whh_t = g_wt[2 + dir];
    float* wsf = sm;
    for (int i = tid; i < 32768; i += 512) {
        int k = i >> 7, col = i & 127;
        float v = whh_t[k * H4 + (col >> 5) * 256 + et * 32 + (col & 31)];
        wsf[((k >> 1) * 128 + col) * 2 + (k & 1)] = v;
    }
    // zero h buffer 0 (each CTA owns 256 contiguous elements); L2-direct
    if (tid < 256) __stcg(&g_h[dir][0][cta * 256 + tid], 0.0f);

    float c_reg = 0.0f;

    group_bar(grp, 8);   // h(0) + flags(=0 from init/reset) visible group-wide

    for (int s = 0; s < TT; s++) {
        int buf = s & 1;

        // prefetch xp into registers (overlaps the flag wait)
        float xq0 = 0.f, xq1 = 0.f, xq2 = 0.f, xq3 = 0.f;
        if (tid < 256) {
            const float* __restrict__ xpp = g_xp + ((size_t)dir * TT + s) * (BB * H4);
            xq0 = xpp[(size_t)b_e * H4 + 0 * 256 + e];
            xq1 = xpp[(size_t)b_e * H4 + 1 * 256 + e];
            xq2 = xpp[(size_t)b_e * H4 + 2 * 256 + e];
            xq3 = xpp[(size_t)b_e * H4 + 3 * 256 + e];
        }

        if (s > 0) {
            // each warp waits only on its producer CTA (= kh) flag
            if ((tid & 31) == 0) {
                const int* fp = &g_flag[grp * 256 + kh * 32];
                while (ld_acq(fp) < s) { }
            }
            __syncwarp();
        }

        // group-local staging: slice floats [kh*32, kh*32+32) for all 8 rows (64 x float4)
        {
            const float* __restrict__ hb = &g_h[dir][buf][b_base * EE];
            int row = tg64 >> 3;             // 0..7
            int c4  = tg64 & 7;              // 0..7
            float4 v = __ldcg((const float4*)&hb[row * 256 + kh * 32] + c4);
            *((float4*)&hs[row * 256 + kh * 32] + c4) = v;
        }
        named_bar(1 + kh, 64);   // group kh's slice staged

        // GEMM: this thread's k-slice (16 k2), 2 cols, all 8 rows; 2 k2 per iter
        ull acc[8][2];
#pragma unroll
        for (int r = 0; r < 8; r++) { acc[r][0] = 0ull; acc[r][1] = 0ull; }

        int k2b = kh * 16;
#pragma unroll
        for (int k2i = 0; k2i < 16; k2i += 2) {
            int k2 = k2b + k2i;
            ulonglong2 wA = *(const ulonglong2*)&ws2[k2 * 128 + 2 * jp];
            ulonglong2 wB = *(const ulonglong2*)&ws2[(k2 + 1) * 128 + 2 * jp];
#pragma unroll
            for (int r = 0; r < 8; r++) {
                ulonglong2 a = *(const ulonglong2*)&hs[r * 256 + 2 * k2];
                fma2(acc[r][0], a.x, wA.x);
                fma2(acc[r][1], a.x, wA.y);
                fma2(acc[r][0], a.y, wB.x);
                fma2(acc[r][1], a.y, wB.y);
            }
        }
        // write k-partials to exchange smem
#pragma unroll
        for (int r = 0; r < 8; r++) {
            float2 pv;
            pv.x = hsum2(acc[r][0]);
            pv.y = hsum2(acc[r][1]);
            *(float2*)&gxp[kh * 1024 + r * 128 + 2 * jp] = pv;
        }
        __syncthreads();   // all 16 warps' gxp writes visible to readers

        if (tid < 256) {
            // elementwise update (c in register), reduce 8 k-partials
            float g0 = xq0, g1 = xq1, g2 = xq2, g3 = xq3;
#pragma unroll
            for (int q = 0; q < 8; q++) {
                g0 += gxp[q * 1024 + bl * 128 + 0 * 32 + el2];
                g1 += gxp[q * 1024 + bl * 128 + 1 * 32 + el2];
                g2 += gxp[q * 1024 + bl * 128 + 2 * 32 + el2];
                g3 += gxp[q * 1024 + bl * 128 + 3 * 32 + el2];
            }
            float iv = fsig(g0);
            float fv = fsig(g1);
            float gv = ftanh(g2);
            float ov = fsig(g3);
            c_reg = fv * c_reg + iv * gv;
            float h = ov * ftanh(c_reg);
            __stcg(&g_h[dir][buf ^ 1][b_e * EE + e], h);   // L2-direct publish

            named_bar(15, 256);                            // h stores done (lower half only)
            if (s < TT - 1 && tid == 0) st_rel(&g_flag[grp * 256 + et * 32], s + 1);

            // g_seq store AFTER release: excluded from the release's store-drain
            int t_out = dir ? (TT - 1 - s) : s;
            __stcg(&g_seq[((size_t)b_e * TT + t_out) * 512 + dir * 256 + e], h);
        }
        // upper warps (kh 4..7) proceed straight to next step's poll/stage:
        // their gxp(s+1) writes are gated by flag(s+1) <- release <- named_bar(15)
        // <- gxp(s) reads, and hs slices are disjoint per kh.
    }

    // terminal barrier, then reset flags for the next graph replay
    group_bar(grp, 8);
    if (tid == 0) g_flag[grp * 256 + et * 32] = 0;
}

// ---------------- kernel 4: LayerNorm + classifier + argmax ----------------
__global__ void ln_logits_kernel(const float* __restrict__ gamma, const float* __restrict__ beta,
                                 const float* __restrict__ cls_w, const float* __restrict__ cls_b,
                                 float* __restrict__ out, int out_size) {
    int tok = blockIdx.x;
    int tid = threadIdx.x;
    int lane = tid & 31;
    int warp = tid >> 5;

    float4 v = ((const float4*)(g_seq + (size_t)tok * 512))[tid];
    float s1 = v.x + v.y + v.z + v.w;
    float s2 = v.x * v.x + v.y * v.y + v.z * v.z + v.w * v.w;
#pragma unroll
    for (int off = 16; off; off >>= 1) {
        s1 += __shfl_down_sync(0xffffffffu, s1, off);
        s2 += __shfl_down_sync(0xffffffffu, s2, off);
    }
    __shared__ float a1[4], a2[4];
    __shared__ float mu_s, rstd_s;
    if (lane == 0) { a1[warp] = s1; a2[warp] = s2; }
    __syncthreads();
    if (tid == 0) {
        float t1 = a1[0] + a1[1] + a1[2] + a1[3];
        float t2 = a2[0] + a2[1] + a2[2] + a2[3];
        float mu = t1 * (1.0f / 512.0f);
        float var = t2 * (1.0f / 512.0f) - mu * mu;
        mu_s = mu;
        rstd_s = rsqrtf(var + 1e-5f);
    }
    __syncthreads();
    float mu = mu_s, rstd = rstd_s;

    float4 gm = ((const float4*)gamma)[tid];
    float4 bt = ((const float4*)beta)[tid];
    float4 y;
    y.x = (v.x - mu) * rstd * gm.x + bt.x;
    y.y = (v.y - mu) * rstd * gm.y + bt.y;
    y.z = (v.z - mu) * rstd * gm.z + bt.z;
    y.w = (v.w - mu) * rstd * gm.w + bt.w;

    float p[KK];
#pragma unroll
    for (int k = 0; k < KK; k++) {
        float4 w = ((const float4*)(cls_w + k * 512))[tid];
        p[k] = y.x * w.x + y.y * w.y + y.z * w.z + y.w * w.w;
    }
#pragma unroll
    for (int off = 16; off; off >>= 1) {
#pragma unroll
        for (int k = 0; k < KK; k++) p[k] += __shfl_down_sync(0xffffffffu, p[k], off);
    }
    __shared__ float wp[4][KK];
    __shared__ float lg[KK];
    if (lane == 0) {
#pragma unroll
        for (int k = 0; k < KK; k++) wp[warp][k] = p[k];
    }
    __syncthreads();
    if (tid < KK) {
        float l = wp[0][tid] + wp[1][tid] + wp[2][tid] + wp[3][tid] + cls_b[tid];
        g_logits[tok * KK + tid] = l;
        lg[tid] = l;
    }
    __syncthreads();
    if (tid == 0) {
        int am = 0;
        float bv = lg[0];
#pragma unroll
        for (int k = 1; k < KK; k++) { if (lg[k] > bv) { bv = lg[k]; am = k; } }
        if (1 + tok < out_size) out[1 + tok] = (float)am;
    }
}

// ---------------- kernel 5: CRF, one warp per batch ----------------
__global__ void crf_kernel(const int* __restrict__ label_ids, const float* __restrict__ crf_start,
                           const float* __restrict__ crf_end, const float* __restrict__ crf_trans) {
    int b = blockIdx.x;
    int lane = threadIdx.x;
    const unsigned FULL = 0xffffffffu;

    float num = 0.0f;
    for (int t = lane; t < TT; t += 32) {
        int tg = label_ids[b * TT + t];
        num += g_logits[(b * TT + t) * KK + tg];
        if (t < TT - 1) num += crf_trans[tg * KK + label_ids[b * TT + t + 1]];
    }
#pragma unroll
    for (int off = 16; off; off >>= 1) num += __shfl_down_sync(FULL, num, off);
    if (lane == 0) {
        num += crf_start[label_ids[b * TT]] + crf_end[label_ids[b * TT + TT - 1]];
    }

    bool act = lane < KK;
    float tcol[KK];
#pragma unroll
    for (int k = 0; k < KK; k++) tcol[k] = act ? crf_trans[k * KK + lane] : 0.0f;
    float alpha = act ? (crf_start[lane] + g_logits[(size_t)b * TT * KK + lane]) : -1e30f;

    for (int t = 1; t < TT; t++) {
        float em = act ? g_logits[((size_t)b * TT + t) * KK + lane] : 0.0f;
        float va[KK];
#pragma unroll
        for (int k = 0; k < KK; k++) va[k] = __shfl_sync(FULL, alpha, k) + tcol[k];
        float m = va[0];
#pragma unroll
        for (int k = 1; k < KK; k++) m = fmaxf(m, va[k]);
        float sme = 0.0f;
#pragma unroll
        for (int k = 0; k < KK; k++) sme += expf(va[k] - m);
        float na = em + m + logf(sme);
        alpha = act ? na : -1e30f;
    }

    float v = act ? (alpha + crf_end[lane]) : -1e30f;
    float m = v;
#pragma unroll
    for (int off = 16; off; off >>= 1) m = fmaxf(m, __shfl_xor_sync(FULL, m, off));
    float e = expf(v - m);
#pragma unroll
    for (int off = 16; off; off >>= 1) e += __shfl_xor_sync(FULL, e, off);
    float logZ = m + logf(e);

    if (lane == 0) g_llh[b] = num - logZ;
}

// ---------------- kernel 6: final loss reduction ----------------
__global__ void loss_kernel(float* __restrict__ out) {
    __shared__ float s[BB];
    int tid = threadIdx.x;
    s[tid] = g_llh[tid];
    __syncthreads();
    for (int off = 32; off; off >>= 1) {
        if (tid < off) s[tid] += s[tid + off];
        __syncthreads();
    }
    if (tid == 0) out[0] = -s[0];
}

// ---------------- launch ----------------
extern "C" void kernel_launch(void* const* d_in, const int* in_sizes, int n_in,
                              void* d_out, int out_size) {
    const int*   word_ids  = (const int*)d_in[0];
    const int*   label_ids = (const int*)d_in[1];
    const float* embed     = (const float*)d_in[2];
    const float* w_ih_f    = (const float*)d_in[3];
    const float* w_hh_f    = (const float*)d_in[4];
    const float* b_f       = (const float*)d_in[5];
    const float* w_ih_b    = (const float*)d_in[6];
    const float* w_hh_b    = (const float*)d_in[7];
    const float* b_b       = (const float*)d_in[8];
    const float* ln_gamma  = (const float*)d_in[9];
    const float* ln_beta   = (const float*)d_in[10];
    const float* cls_w     = (const float*)d_in[11];
    const float* cls_b     = (const float*)d_in[12];
    const float* crf_start = (const float*)d_in[13];
    const float* crf_end   = (const float*)d_in[14];
    const float* crf_trans = (const float*)d_in[15];
    float* out = (float*)d_out;

    const int PROJ_SMEM = (16384 + 32768) * 4;          // 196608 B
    const int LSTM_SMEM = (32768 + 2048 + 8192) * 4;    // 172032 B
    cudaFuncSetAttribute(proj_kernel, cudaFuncAttributeMaxDynamicSharedMemorySize, PROJ_SMEM);
    cudaFuncSetAttribute(lstm_kernel, cudaFuncAttributeMaxDynamicSharedMemorySize, LSTM_SMEM);

    transpose_w_kernel<<<4096, 256>>>(w_ih_f, w_ih_b, w_hh_f, w_hh_b);
    proj_kernel<<<dim3(512, 4, 2), 512, PROJ_SMEM>>>(word_ids, embed, b_f, b_b);
    lstm_kernel<<<dim3(64, 2), 512, LSTM_SMEM>>>();
    ln_logits_kernel<<<32768, 128>>>(ln_gamma, ln_beta, cls_w, cls_b, out, out_size);
    crf_kernel<<<BB, 32>>>(label_ids, crf_start, crf_end, crf_trans);
    loss_kernel<<<1, BB>>>(out);
}

// round 17
// speedup vs baseline: 2.0654x; 1.0225x over previous
#include <cuda_runtime.h>
#include <cstdint>

#define BB 64
#define TT 512
#define EE 256
#define H4 1024
#define KK 9

typedef unsigned long long ull;

// ---------------- device scratch (static) ----------------
// ih weights (idx 0,1): paired layout  float[((k>>1)*H4 + j)*2 + (k&1)]  == ull[k2*H4 + j]
// hh weights (idx 2,3): plain          float[k*H4 + j]
__device__ float g_wt[4][EE * H4];
__device__ float g_xp[2 * TT * BB * H4];       // [dir][step][b][j]
__device__ float g_seq[(size_t)BB * TT * 512]; // [b][t][2H]
__device__ float g_h[2][2][BB * EE];           // [dir][parity][b*E+e]
__device__ float g_logits[BB * TT * KK];
__device__ float g_llh[BB];
// per-(dir,bt)-group step flags: flag[grp*256 + et*32] = steps published (monotone in-run)
__device__ int g_flag[16 * 256];
// init/terminal barrier (gen snapshot-compared -> replay-safe)
__device__ int g_bar_count[16 * 32];
__device__ int g_bar_gen[16 * 32];

__device__ __forceinline__ float fsig(float x) {
    return __fdividef(1.0f, 1.0f + __expf(-x));
}
__device__ __forceinline__ float ftanh(float x) {
    return __fdividef(2.0f, 1.0f + __expf(-2.0f * x)) - 1.0f;
}

__device__ __forceinline__ void fma2(ull& d, ull a, ull b) {
    asm("fma.rn.f32x2 %0, %1, %2, %0;" : "+l"(d) : "l"(a), "l"(b));
}
__device__ __forceinline__ float hsum2(ull v) {
    float lo, hi;
    asm("mov.b64 {%0,%1}, %2;" : "=f"(lo), "=f"(hi) : "l"(v));
    return lo + hi;
}

// strong-GPU flag ops: no fence instruction, no CCTL.IVALL (L1 untouched)
__device__ __forceinline__ int ld_acq(const int* p) {
    int v;
    asm volatile("ld.acquire.gpu.global.b32 %0, [%1];" : "=r"(v) : "l"(p) : "memory");
    return v;
}
__device__ __forceinline__ void st_rel(int* p, int v) {
    asm volatile("st.release.gpu.global.b32 [%0], %1;" :: "l"(p), "r"(v) : "memory");
}
__device__ __forceinline__ void named_bar(int id, int cnt) {
    asm volatile("bar.sync %0, %1;" :: "r"(id), "r"(cnt) : "memory");
}

// ---------------- group barrier (init/terminal use only) ----------------
__device__ __forceinline__ void group_bar(int id, int n) {
    __syncthreads();
    if (threadIdx.x == 0) {
        int* cnt = &g_bar_count[id * 32];
        int* gen = &g_bar_gen[id * 32];
        int g0 = *(volatile int*)gen;
        __threadfence();
        int t = atomicAdd(cnt, 1);
        if (t == n - 1) {
            *cnt = 0;
            __threadfence();
            atomicAdd(gen, 1);
        } else {
            while (*(volatile int*)gen == g0) { __nanosleep(32); }
            __threadfence();
        }
    }
    __syncthreads();
}

// ---------------- kernel 1: weight transpose/pack ----------------
__global__ void transpose_w_kernel(const float* __restrict__ wf, const float* __restrict__ wb,
                                   const float* __restrict__ whf, const float* __restrict__ whb) {
    int idx = blockIdx.x * 256 + threadIdx.x;      // 4 * 262144 total
    int srcid = idx >> 18;
    int m = idx & 262143;
    int k = m >> 10;
    int j = m & 1023;
    const float* src = (srcid == 0) ? wf : (srcid == 1) ? wb : (srcid == 2) ? whf : whb;
    float v = src[j * EE + k];
    if (srcid < 2) g_wt[srcid][((k >> 1) * H4 + j) * 2 + (k & 1)] = v;   // paired over k
    else           g_wt[srcid][k * H4 + j] = v;                          // plain
}

// ---------------- kernel 2: embedding gather + input projections (f32x2) ----------------
// grid (512 s-tiles, 4 j-tiles of 256, 2 dirs), 512 threads.
__global__ void __launch_bounds__(512, 1) proj_kernel(const int* __restrict__ word_ids,
                                                      const float* __restrict__ embed,
                                                      const float* __restrict__ b_f,
                                                      const float* __restrict__ b_b) {
    extern __shared__ float psm[];
    float* esf = psm;                  // [64][256]   = 16384 floats
    ull*   wsm = (ull*)(psm + 16384);  // [64 k2][256 j] ull = 32768 floats
    __shared__ int wids[64];

    int dir = blockIdx.z;
    int jt  = blockIdx.y;             // j base jt*256
    int s   = blockIdx.x;             // one timestep, all 64 batch rows
    int t_src = dir ? (TT - 1 - s) : s;
    int tid = threadIdx.x;
    int jb = jt * 256;

    if (tid < 64) wids[tid] = word_ids[tid * TT + t_src];
    __syncthreads();
    for (int i = tid; i < 4096; i += 512) {
        int r = i >> 6, c = i & 63;
        ((float4*)&esf[r * 256])[c] = ((const float4*)(embed + (size_t)wids[r] * EE))[c];
    }

    int tg = tid >> 6;                // 0..7 -> tokens tg*8..tg*8+7
    int jq = tid & 63;                // -> j cols jb + jq*4 .. +3

    ull acc[8][4];
#pragma unroll
    for (int r = 0; r < 8; r++)
#pragma unroll
        for (int c = 0; c < 4; c++) acc[r][c] = 0ull;

    const float4* __restrict__ gw4 = (const float4*)g_wt[dir];

    for (int kc = 0; kc < 2; kc++) {
        __syncthreads();
        for (int i = tid; i < 8192; i += 512) {
            int k2l = i >> 7;
            int jj4 = i & 127;
            ((float4*)wsm)[i] = gw4[((size_t)((kc * 64 + k2l) * H4 + jb) >> 1) + jj4];
        }
        __syncthreads();

#pragma unroll 4
        for (int k2l = 0; k2l < 64; k2l += 2) {
            int kabs4 = kc * 128 + 2 * k2l;
            ulonglong2 a[8];
#pragma unroll
            for (int r = 0; r < 8; r++)
                a[r] = *(const ulonglong2*)&esf[(tg * 8 + r) * 256 + kabs4];
            const ull* wpA = &wsm[k2l * 256 + jq * 4];
            const ull* wpB = &wsm[(k2l + 1) * 256 + jq * 4];
            ulonglong2 wA01 = *(const ulonglong2*)wpA;
            ulonglong2 wA23 = *(const ulonglong2*)(wpA + 2);
            ulonglong2 wB01 = *(const ulonglong2*)wpB;
            ulonglong2 wB23 = *(const ulonglong2*)(wpB + 2);
#pragma unroll
            for (int r = 0; r < 8; r++) {
                fma2(acc[r][0], a[r].x, wA01.x);
                fma2(acc[r][1], a[r].x, wA01.y);
                fma2(acc[r][2], a[r].x, wA23.x);
                fma2(acc[r][3], a[r].x, wA23.y);
                fma2(acc[r][0], a[r].y, wB01.x);
                fma2(acc[r][1], a[r].y, wB01.y);
                fma2(acc[r][2], a[r].y, wB23.x);
                fma2(acc[r][3], a[r].y, wB23.y);
            }
        }
    }

    const float* bias_p = dir ? b_b : b_f;
    int j0 = jb + jq * 4;
    float4 bias = *(const float4*)&bias_p[j0];
    size_t base = ((size_t)dir * TT + s) * (BB * H4);
#pragma unroll
    for (int r = 0; r < 8; r++) {
        int b = tg * 8 + r;
        float4 v;
        v.x = hsum2(acc[r][0]) + bias.x;
        v.y = hsum2(acc[r][1]) + bias.y;
        v.z = hsum2(acc[r][2]) + bias.z;
        v.w = hsum2(acc[r][3]) + bias.w;
        *(float4*)&g_xp[base + (size_t)b * H4 + j0] = v;
    }
}

// ---------------- kernel 3: persistent BiLSTM (unchanged from R16 best) ----------------
__global__ void __launch_bounds__(512, 1) lstm_kernel() {
    extern __shared__ float sm[];
    ull*   ws2 = (ull*)sm;            // [128 k2][128 col] ull  (131072 B)
    float* hs  = sm + 32768;          // [8][256]               (8192 B)
    float* gxp = sm + 32768 + 2048;   // [8 kh][8 row][128 col] (32768 B)

    int dir = blockIdx.y;
    int cta = blockIdx.x;
    int bt = cta >> 3;
    int et = cta & 7;
    int b_base = bt * 8;
    int grp = dir * 8 + bt;
    int tid = threadIdx.x;

    int jp = tid & 63;
    int kh = tid >> 6;
    int tg64 = tid & 63;

    int bl = tid >> 5;
    int el2 = tid & 31;
    int b_e = b_base + (bl & 7);
    int e = et * 32 + el2;

    const float* __restrict__ whh_t = g_wt[2 + dir];
    float* wsf = sm;
    for (int i = tid; i < 32768; i += 512) {
        int k = i >> 7, col = i & 127;
        float v = whh_t[k * H4 + (col >> 5) * 256 + et * 32 + (col & 31)];
        wsf[((k >> 1) * 128 + col) * 2 + (k & 1)] = v;
    }
    if (tid < 256) __stcg(&g_h[dir][0][cta * 256 + tid], 0.0f);

    float c_reg = 0.0f;

    group_bar(grp, 8);

    for (int s = 0; s < TT; s++) {
        int buf = s & 1;

        float xq0 = 0.f, xq1 = 0.f, xq2 = 0.f, xq3 = 0.f;
        if (tid < 256) {
            const float* __restrict__ xpp = g_xp + ((size_t)dir * TT + s) * (BB * H4);
            xq0 = xpp[(size_t)b_e * H4 + 0 * 256 + e];
            xq1 = xpp[(size_t)b_e * H4 + 1 * 256 + e];
            xq2 = xpp[(size_t)b_e * H4 + 2 * 256 + e];
            xq3 = xpp[(size_t)b_e * H4 + 3 * 256 + e];
        }

        if (s > 0) {
            if ((tid & 31) == 0) {
                const int* fp = &g_flag[grp * 256 + kh * 32];
                while (ld_acq(fp) < s) { }
            }
            __syncwarp();
        }

        {
            const float* __restrict__ hb = &g_h[dir][buf][b_base * EE];
            int row = tg64 >> 3;
            int c4  = tg64 & 7;
            float4 v = __ldcg((const float4*)&hb[row * 256 + kh * 32] + c4);
            *((float4*)&hs[row * 256 + kh * 32] + c4) = v;
        }
        named_bar(1 + kh, 64);

        ull acc[8][2];
#pragma unroll
        for (int r = 0; r < 8; r++) { acc[r][0] = 0ull; acc[r][1] = 0ull; }

        int k2b = kh * 16;
#pragma unroll
        for (int k2i = 0; k2i < 16; k2i += 2) {
            int k2 = k2b + k2i;
            ulonglong2 wA = *(const ulonglong2*)&ws2[k2 * 128 + 2 * jp];
            ulonglong2 wB = *(const ulonglong2*)&ws2[(k2 + 1) * 128 + 2 * jp];
#pragma unroll
            for (int r = 0; r < 8; r++) {
                ulonglong2 a = *(const ulonglong2*)&hs[r * 256 + 2 * k2];
                fma2(acc[r][0], a.x, wA.x);
                fma2(acc[r][1], a.x, wA.y);
                fma2(acc[r][0], a.y, wB.x);
                fma2(acc[r][1], a.y, wB.y);
            }
        }
#pragma unroll
        for (int r = 0; r < 8; r++) {
            float2 pv;
            pv.x = hsum2(acc[r][0]);
            pv.y = hsum2(acc[r][1]);
            *(float2*)&gxp[kh * 1024 + r * 128 + 2 * jp] = pv;
        }
        __syncthreads();

        if (tid < 256) {
            float g0 = xq0, g1 = xq1, g2 = xq2, g3 = xq3;
#pragma unroll
            for (int q = 0; q < 8; q++) {
                g0 += gxp[q * 1024 + bl * 128 + 0 * 32 + el2];
                g1 += gxp[q * 1024 + bl * 128 + 1 * 32 + el2];
                g2 += gxp[q * 1024 + bl * 128 + 2 * 32 + el2];
                g3 += gxp[q * 1024 + bl * 128 + 3 * 32 + el2];
            }
            float iv = fsig(g0);
            float fv = fsig(g1);
            float gv = ftanh(g2);
            float ov = fsig(g3);
            c_reg = fv * c_reg + iv * gv;
            float h = ov * ftanh(c_reg);
            __stcg(&g_h[dir][buf ^ 1][b_e * EE + e], h);

            named_bar(15, 256);
            if (s < TT - 1 && tid == 0) st_rel(&g_flag[grp * 256 + et * 32], s + 1);

            int t_out = dir ? (TT - 1 - s) : s;
            __stcg(&g_seq[((size_t)b_e * TT + t_out) * 512 + dir * 256 + e], h);
        }
    }

    group_bar(grp, 8);
    if (tid == 0) g_flag[grp * 256 + et * 32] = 0;
}

// ---------------- kernel 4: LayerNorm + classifier + argmax (warp per token) ----------------
// grid 8192 x 128 threads: 4 warps/block, each warp owns one token. No smem, no syncthreads.
__global__ void __launch_bounds__(128) ln_logits_kernel(
        const float* __restrict__ gamma, const float* __restrict__ beta,
        const float* __restrict__ cls_w, const float* __restrict__ cls_b,
        float* __restrict__ out, int out_size) {
    const unsigned FULL = 0xffffffffu;
    int lane = threadIdx.x & 31;
    int tok = blockIdx.x * 4 + (threadIdx.x >> 5);

    // each lane: 4 float4 = 16 floats of the 512-long feature
    const float4* vp = (const float4*)(g_seq + (size_t)tok * 512);
    float4 v[4];
#pragma unroll
    for (int i = 0; i < 4; i++) v[i] = vp[i * 32 + lane];

    float s1 = 0.f, s2 = 0.f;
#pragma unroll
    for (int i = 0; i < 4; i++) {
        s1 += v[i].x + v[i].y + v[i].z + v[i].w;
        s2 += v[i].x * v[i].x + v[i].y * v[i].y + v[i].z * v[i].z + v[i].w * v[i].w;
    }
#pragma unroll
    for (int off = 16; off; off >>= 1) {
        s1 += __shfl_xor_sync(FULL, s1, off);
        s2 += __shfl_xor_sync(FULL, s2, off);
    }
    float mu = s1 * (1.0f / 512.0f);
    float var = s2 * (1.0f / 512.0f) - mu * mu;
    float rstd = rsqrtf(var + 1e-5f);

    // normalized features (gamma/beta hot in L1)
    const float4* gp = (const float4*)gamma;
    const float4* bp = (const float4*)beta;
    float4 y[4];
#pragma unroll
    for (int i = 0; i < 4; i++) {
        float4 gm = gp[i * 32 + lane];
        float4 bt = bp[i * 32 + lane];
        y[i].x = (v[i].x - mu) * rstd * gm.x + bt.x;
        y[i].y = (v[i].y - mu) * rstd * gm.y + bt.y;
        y[i].z = (v[i].z - mu) * rstd * gm.z + bt.z;
        y[i].w = (v[i].w - mu) * rstd * gm.w + bt.w;
    }

    float p[KK];
#pragma unroll
    for (int k = 0; k < KK; k++) {
        const float4* wp = (const float4*)(cls_w + k * 512);
        float acc = 0.f;
#pragma unroll
        for (int i = 0; i < 4; i++) {
            float4 w = wp[i * 32 + lane];
            acc += y[i].x * w.x + y[i].y * w.y + y[i].z * w.z + y[i].w * w.w;
        }
        p[k] = acc;
    }
#pragma unroll
    for (int off = 16; off; off >>= 1) {
#pragma unroll
        for (int k = 0; k < KK; k++) p[k] += __shfl_xor_sync(FULL, p[k], off);
    }

    if (lane == 0) {
        float lg[KK];
        int am = 0;
        float bv = -1e30f;
#pragma unroll
        for (int k = 0; k < KK; k++) {
            lg[k] = p[k] + __ldg(&cls_b[k]);
            g_logits[tok * KK + k] = lg[k];
            if (lg[k] > bv) { bv = lg[k]; am = k; }
        }
        if (1 + tok < out_size) out[1 + tok] = (float)am;
    }
}

// ---------------- kernel 5: CRF, one warp per batch (fast-math transcendentals) ----------------
__global__ void crf_kernel(const int* __restrict__ label_ids, const float* __restrict__ crf_start,
                           const float* __restrict__ crf_end, const float* __restrict__ crf_trans) {
    int b = blockIdx.x;
    int lane = threadIdx.x;
    const unsigned FULL = 0xffffffffu;

    float num = 0.0f;
    for (int t = lane; t < TT; t += 32) {
        int tg = label_ids[b * TT + t];
        num += g_logits[(b * TT + t) * KK + tg];
        if (t < TT - 1) num += crf_trans[tg * KK + label_ids[b * TT + t + 1]];
    }
#pragma unroll
    for (int off = 16; off; off >>= 1) num += __shfl_down_sync(FULL, num, off);
    if (lane == 0) {
        num += crf_start[label_ids[b * TT]] + crf_end[label_ids[b * TT + TT - 1]];
    }

    bool act = lane < KK;
    float tcol[KK];
#pragma unroll
    for (int k = 0; k < KK; k++) tcol[k] = act ? crf_trans[k * KK + lane] : 0.0f;
    float alpha = act ? (crf_start[lane] + g_logits[(size_t)b * TT * KK + lane]) : -1e30f;

    for (int t = 1; t < TT; t++) {
        float em = act ? g_logits[((size_t)b * TT + t) * KK + lane] : 0.0f;
        float va[KK];
#pragma unroll
        for (int k = 0; k < KK; k++) va[k] = __shfl_sync(FULL, alpha, k) + tcol[k];
        float m = va[0];
#pragma unroll
        for (int k = 1; k < KK; k++) m = fmaxf(m, va[k]);
        float sme = 0.0f;
#pragma unroll
        for (int k = 0; k < KK; k++) sme += __expf(va[k] - m);
        float na = em + m + __logf(sme);
        alpha = act ? na : -1e30f;
    }

    float v = act ? (alpha + crf_end[lane]) : -1e30f;
    float m = v;
#pragma unroll
    for (int off = 16; off; off >>= 1) m = fmaxf(m, __shfl_xor_sync(FULL, m, off));
    float e = __expf(v - m);
#pragma unroll
    for (int off = 16; off; off >>= 1) e += __shfl_xor_sync(FULL, e, off);
    float logZ = m + __logf(e);

    if (lane == 0) g_llh[b] = num - logZ;
}

// ---------------- kernel 6: final loss reduction ----------------
__global__ void loss_kernel(float* __restrict__ out) {
    __shared__ float s[BB];
    int tid = threadIdx.x;
    s[tid] = g_llh[tid];
    __syncthreads();
    for (int off = 32; off; off >>= 1) {
        if (tid < off) s[tid] += s[tid + off];
        __syncthreads();
    }
    if (tid == 0) out[0] = -s[0];
}

// ---------------- launch ----------------
extern "C" void kernel_launch(void* const* d_in, const int* in_sizes, int n_in,
                              void* d_out, int out_size) {
    const int*   word_ids  = (const int*)d_in[0];
    const int*   label_ids = (const int*)d_in[1];
    const float* embed     = (const float*)d_in[2];
    const float* w_ih_f    = (const float*)d_in[3];
    const float* w_hh_f    = (const float*)d_in[4];
    const float* b_f       = (const float*)d_in[5];
    const float* w_ih_b    = (const float*)d_in[6];
    const float* w_hh_b    = (const float*)d_in[7];
    const float* b_b       = (const float*)d_in[8];
    const float* ln_gamma  = (const float*)d_in[9];
    const float* ln_beta   = (const float*)d_in[10];
    const float* cls_w     = (const float*)d_in[11];
    const float* cls_b     = (const float*)d_in[12];
    const float* crf_start = (const float*)d_in[13];
    const float* crf_end   = (const float*)d_in[14];
    const float* crf_trans = (const float*)d_in[15];
    float* out = (float*)d_out;

    const int PROJ_SMEM = (16384 + 32768) * 4;          // 196608 B
    const int LSTM_SMEM = (32768 + 2048 + 8192) * 4;    // 172032 B
    cudaFuncSetAttribute(proj_kernel, cudaFuncAttributeMaxDynamicSharedMemorySize, PROJ_SMEM);
    cudaFuncSetAttribute(lstm_kernel, cudaFuncAttributeMaxDynamicSharedMemorySize, LSTM_SMEM);

    transpose_w_kernel<<<4096, 256>>>(w_ih_f, w_ih_b, w_hh_f, w_hh_b);
    proj_kernel<<<dim3(512, 4, 2), 512, PROJ_SMEM>>>(word_ids, embed, b_f, b_b);
    lstm_kernel<<<dim3(64, 2), 512, LSTM_SMEM>>>();
    ln_logits_kernel<<<8192, 128>>>(ln_gamma, ln_beta, cls_w, cls_b, out, out_size);
    crf_kernel<<<BB, 32>>>(label_ids, crf_start, crf_end, crf_trans);
    loss_kernel<<<1, BB>>>(out);
}